// round 10
// baseline (speedup 1.0000x reference)
#include <cuda_runtime.h>
#include <cuda_bf16.h>
#include <math.h>
#include <stdint.h>

#define A_NUM   9
#define C_NUM   20
#define OUTCH   65
#define BATCH   32
#define KDIM    256
#define HH      56
#define WW      56
#define HW      3136
#define NBOX    64
#define MPOS    2048

// ---- global scratch ----
__device__ __nv_bfloat16 g_w1_hi[KDIM * KDIM];
__device__ __nv_bfloat16 g_w1_lo[KDIM * KDIM];
__device__ __nv_bfloat16 g_w2_hi[OUTCH * KDIM];
__device__ __nv_bfloat16 g_w2_lo[OUTCH * KDIM];
__device__ __nv_bfloat16 g_feat_hi[(size_t)BATCH * KDIM * HW];
__device__ __nv_bfloat16 g_feat_lo[(size_t)BATCH * KDIM * HW];
__device__ __nv_bfloat16 g_hid_hi[(size_t)BATCH * KDIM * HW];   // [b][m][p]
__device__ __nv_bfloat16 g_hid_lo[(size_t)BATCH * KDIM * HW];
__device__ float         g_out2 [(size_t)BATCH * OUTCH * HW];   // [b][m][p]
__device__ float         g_loss_part[32];

// ---- helpers ----
__device__ __forceinline__ uint32_t smem_u32(const void* p) {
    uint32_t a;
    asm("{ .reg .u64 t; cvta.to.shared.u64 t, %1; cvt.u32.u64 %0, t; }"
        : "=r"(a) : "l"(p));
    return a;
}
__device__ __forceinline__ uint32_t pk2(__nv_bfloat16 a, __nv_bfloat16 b) {
    __nv_bfloat162 t; t.x = a; t.y = b;
    return *(uint32_t*)&t;
}
__device__ __forceinline__ void split1(float x, __nv_bfloat16& h, __nv_bfloat16& l) {
    h = __float2bfloat16(x);
    l = __float2bfloat16(x - __bfloat162float(h));
}
__device__ __forceinline__ void mma16816(float* c,
    const uint32_t* a, uint32_t b0, uint32_t b1)
{
    asm volatile(
        "mma.sync.aligned.m16n8k16.row.col.f32.bf16.bf16.f32 "
        "{%0,%1,%2,%3}, {%4,%5,%6,%7}, {%8,%9}, {%0,%1,%2,%3};"
        : "+f"(c[0]), "+f"(c[1]), "+f"(c[2]), "+f"(c[3])
        : "r"(a[0]), "r"(a[1]), "r"(a[2]), "r"(a[3]), "r"(b0), "r"(b1));
}
__device__ __forceinline__ void ldmx4(uint32_t* r, uint32_t addr) {
    asm volatile("ldmatrix.sync.aligned.m8n8.x4.shared.b16 {%0,%1,%2,%3}, [%4];"
        : "=r"(r[0]), "=r"(r[1]), "=r"(r[2]), "=r"(r[3]) : "r"(addr));
}
__device__ __forceinline__ void ldmx4t(uint32_t* r, uint32_t addr) {
    asm volatile("ldmatrix.sync.aligned.m8n8.x4.trans.shared.b16 {%0,%1,%2,%3}, [%4];"
        : "=r"(r[0]), "=r"(r[1]), "=r"(r[2]), "=r"(r[3]) : "r"(addr));
}
__device__ __forceinline__ void cpa16(uint32_t dst, const void* src, bool ok) {
    uint32_t sz = ok ? 16u : 0u;
    asm volatile("cp.async.cg.shared.global [%0], [%1], 16, %2;"
                 :: "r"(dst), "l"(src), "r"(sz));
}
__device__ __forceinline__ void cpa_commit() {
    asm volatile("cp.async.commit_group;" ::: "memory");
}
__device__ __forceinline__ void cpa_wait1() {
    asm volatile("cp.async.wait_group 1;" ::: "memory");
}

#define APITCH 80

// ---------------------------------------------------------------------------
__global__ __launch_bounds__(256)
void convert_split(const float* __restrict__ src,
                   __nv_bfloat16* __restrict__ hi,
                   __nv_bfloat16* __restrict__ lo, int n4)
{
    int t = blockIdx.x * blockDim.x + threadIdx.x;
    if (t >= n4) return;
    float4 v = ((const float4*)src)[t];
    __nv_bfloat16 h0, h1, h2, h3, l0, l1, l2, l3;
    split1(v.x, h0, l0); split1(v.y, h1, l1);
    split1(v.z, h2, l2); split1(v.w, h3, l3);
    ((uint2*)hi)[t] = make_uint2(pk2(h0, h1), pk2(h2, h3));
    ((uint2*)lo)[t] = make_uint2(pk2(l0, l1), pk2(l2, l3));
}

// ---------------------------------------------------------------------------
// Pipelined split-bf16 HMMA GEMM. Warp tile 64x64, 8 warps, BK=32,
// 2-stage cp.async, 1 CTA/SM (255-reg budget, acc=128 regs).
// GEMM1: BM=256, BN=128 (4x2 warps). GEMM2: BM=128, BN=256 (2x4 warps).
// Per chunk: wait1 -> sync -> compute(c) -> sync -> issue(c+2) -> commit.
// ---------------------------------------------------------------------------
template<int BM, int BN, int MROWS, bool FIRST>
__global__ __launch_bounds__(256, 1)
void gemm_pipe(const __nv_bfloat16* __restrict__ Ahi_g,
               const __nv_bfloat16* __restrict__ Alo_g,
               const __nv_bfloat16* __restrict__ Bhi_g,
               const __nv_bfloat16* __restrict__ Blo_g,
               const float* __restrict__ bias)
{
    constexpr int WN  = BN / 64;                 // warps along n
    constexpr int BP  = BN * 2 + 16;             // B row pitch (bytes)
    constexpr int AHI = 0;
    constexpr int ALO = BM * APITCH;
    constexpr int BHI = 2 * BM * APITCH;
    constexpr int BLO = 2 * BM * APITCH + 32 * BP;
    constexpr int STG = 2 * BM * APITCH + 64 * BP;
    constexpr int AQ  = BM / 64;                 // A 16B-chunks / thread / half
    constexpr int BQ  = BN / 64;                 // B 16B-chunks / thread / half

    extern __shared__ char smem[];
    const uint32_t sb = smem_u32(smem);

    const int b     = blockIdx.z;
    const int mBase = blockIdx.y * BM;
    const int nBase = blockIdx.x * BN;
    const int tid   = threadIdx.x;
    const int wid   = tid >> 5;
    const int lane  = tid & 31;
    const int wm    = wid / WN;
    const int wn    = wid % WN;

    const size_t bofs = (size_t)b * KDIM * HW;

    // loader precompute
    size_t  aOff[AQ]; bool aOk[AQ]; uint32_t aDst[AQ];
    #pragma unroll
    for (int q = 0; q < AQ; q++) {
        int e = tid + q * 256, row = e >> 2, c = e & 3;
        aOk[q]  = (mBase + row) < MROWS;
        aOff[q] = aOk[q] ? ((size_t)(mBase + row) * KDIM + c * 8) : 0;
        aDst[q] = row * APITCH + c * 16;
    }
    size_t  bOff[BQ]; bool bOk[BQ]; uint32_t bDst[BQ];
    #pragma unroll
    for (int q = 0; q < BQ; q++) {
        int e = tid + q * 256, row = e / (BN / 8), col = e % (BN / 8);
        int p = nBase + col * 8;
        bOk[q]  = p < HW;
        bOff[q] = bofs + (bOk[q] ? ((size_t)row * HW + p) : 0);
        bDst[q] = row * BP + col * 16;
    }

    float acc[4][8][4];
    #pragma unroll
    for (int i = 0; i < 4; i++)
        #pragma unroll
        for (int j = 0; j < 8; j++)
            #pragma unroll
            for (int q = 0; q < 4; q++) acc[i][j][q] = 0.f;

    #define ISSUE_CHUNK(ST, KO)                                                   \
        do {                                                                      \
            _Pragma("unroll")                                                     \
            for (int q = 0; q < AQ; q++) {                                        \
                cpa16((ST) + AHI + aDst[q], Ahi_g + aOff[q] + (KO), aOk[q]);      \
                cpa16((ST) + ALO + aDst[q], Alo_g + aOff[q] + (KO), aOk[q]);      \
            }                                                                     \
            _Pragma("unroll")                                                     \
            for (int q = 0; q < BQ; q++) {                                        \
                cpa16((ST) + BHI + bDst[q], Bhi_g + bOff[q] + (size_t)(KO) * HW, bOk[q]); \
                cpa16((ST) + BLO + bDst[q], Blo_g + bOff[q] + (size_t)(KO) * HW, bOk[q]); \
            }                                                                     \
        } while (0)

    ISSUE_CHUNK(sb, 0);
    cpa_commit();
    ISSUE_CHUNK(sb + STG, 32);
    cpa_commit();

    // warp-uniform m-frag validity (prunes GEMM2 padding work)
    bool vi[4];
    #pragma unroll
    for (int i = 0; i < 4; i++)
        vi[i] = FIRST ? true : ((mBase + wm * 64 + i * 16) < MROWS);

    const int lane15 = lane & 15;
    const int laneHi = lane >> 4;
    const int kB     = (lane >> 3) & 1;
    const int lane7  = lane & 7;
    const uint32_t aFragBase = (wm * 64 + lane15) * APITCH + laneHi * 16;
    const uint32_t bFragRow  = kB * 8 + lane7;
    const uint32_t bFragCol  = (wn * 64 + laneHi * 8) * 2;

    #pragma unroll 1
    for (int c = 0; c < 8; c++) {
        cpa_wait1();          // chunk c copies (own groups) done
        __syncthreads();      // publish chunk c across all threads
        const uint32_t st = sb + (c & 1) * STG;

        #pragma unroll
        for (int ks = 0; ks < 2; ks++) {
            uint32_t ah[4][4], bh[8][2];
            #pragma unroll
            for (int i = 0; i < 4; i++)
                if (vi[i])
                    ldmx4(ah[i], st + AHI + aFragBase + i * 16 * APITCH + ks * 32);
            #pragma unroll
            for (int jj = 0; jj < 4; jj++) {
                uint32_t r[4];
                ldmx4t(r, st + BHI + (ks * 16 + bFragRow) * BP + bFragCol + jj * 32);
                bh[jj * 2][0] = r[0]; bh[jj * 2][1] = r[1];
                bh[jj * 2 + 1][0] = r[2]; bh[jj * 2 + 1][1] = r[3];
            }
            #pragma unroll
            for (int i = 0; i < 4; i++)
                if (vi[i])
                    #pragma unroll
                    for (int j = 0; j < 8; j++)
                        mma16816(acc[i][j], ah[i], bh[j][0], bh[j][1]);
            {
                uint32_t bl[8][2];
                #pragma unroll
                for (int jj = 0; jj < 4; jj++) {
                    uint32_t r[4];
                    ldmx4t(r, st + BLO + (ks * 16 + bFragRow) * BP + bFragCol + jj * 32);
                    bl[jj * 2][0] = r[0]; bl[jj * 2][1] = r[1];
                    bl[jj * 2 + 1][0] = r[2]; bl[jj * 2 + 1][1] = r[3];
                }
                #pragma unroll
                for (int i = 0; i < 4; i++)
                    if (vi[i])
                        #pragma unroll
                        for (int j = 0; j < 8; j++)
                            mma16816(acc[i][j], ah[i], bl[j][0], bl[j][1]);
            }
            {
                uint32_t al[4];
                #pragma unroll
                for (int i = 0; i < 4; i++)
                    if (vi[i]) {
                        ldmx4(al, st + ALO + aFragBase + i * 16 * APITCH + ks * 32);
                        #pragma unroll
                        for (int j = 0; j < 8; j++)
                            mma16816(acc[i][j], al, bh[j][0], bh[j][1]);
                    }
            }
        }

        __syncthreads();      // all warps done reading buffer c&1 before refill
        if (c + 2 < 8) {
            const uint32_t st2 = sb + (c & 1) * STG;
            const int ko = (c + 2) * 32;
            ISSUE_CHUNK(st2, ko);
        }
        cpa_commit();
    }
    #undef ISSUE_CHUNK

    // ---- epilogue ----
    const int g   = lane >> 2;
    const int tig = lane & 3;
    #pragma unroll
    for (int i = 0; i < 4; i++) {
        const int m0 = mBase + wm * 64 + i * 16 + g;
        if (FIRST) {
            const float bv0 = bias[m0];
            const float bv1 = bias[m0 + 8];
            #pragma unroll
            for (int j = 0; j < 8; j++) {
                int p = nBase + wn * 64 + j * 8 + tig * 2;
                if (p < HW) {
                    float f0 = acc[i][j][0] + bv0; f0 = f0 >= 0.f ? f0 : 0.01f * f0;
                    float f1 = acc[i][j][1] + bv0; f1 = f1 >= 0.f ? f1 : 0.01f * f1;
                    float f2 = acc[i][j][2] + bv1; f2 = f2 >= 0.f ? f2 : 0.01f * f2;
                    float f3 = acc[i][j][3] + bv1; f3 = f3 >= 0.f ? f3 : 0.01f * f3;
                    __nv_bfloat16 h0, h1, h2, h3, l0, l1, l2, l3;
                    split1(f0, h0, l0); split1(f1, h1, l1);
                    split1(f2, h2, l2); split1(f3, h3, l3);
                    size_t o0 = bofs + (size_t)m0 * HW + p;
                    size_t o1 = bofs + (size_t)(m0 + 8) * HW + p;
                    *(uint32_t*)&g_hid_hi[o0] = pk2(h0, h1);
                    *(uint32_t*)&g_hid_lo[o0] = pk2(l0, l1);
                    *(uint32_t*)&g_hid_hi[o1] = pk2(h2, h3);
                    *(uint32_t*)&g_hid_lo[o1] = pk2(l2, l3);
                }
            }
        } else {
            const bool ok0 = m0 < MROWS;
            const bool ok1 = (m0 + 8) < MROWS;
            if (!ok0 && !ok1) continue;
            const float bv0 = ok0 ? bias[m0] : 0.f;
            const float bv1 = ok1 ? bias[m0 + 8] : 0.f;
            #pragma unroll
            for (int j = 0; j < 8; j++) {
                int p = nBase + wn * 64 + j * 8 + tig * 2;
                if (p < HW) {
                    if (ok0) {
                        float2 v = make_float2(acc[i][j][0] + bv0, acc[i][j][1] + bv0);
                        *(float2*)&g_out2[((size_t)b * OUTCH + m0) * HW + p] = v;
                    }
                    if (ok1) {
                        float2 v = make_float2(acc[i][j][2] + bv1, acc[i][j][3] + bv1);
                        *(float2*)&g_out2[((size_t)b * OUTCH + m0 + 8) * HW + p] = v;
                    }
                }
            }
        }
    }
}

// ---------------------------------------------------------------------------
__global__ __launch_bounds__(256)
void head_kernel(const float* __restrict__ anc,
                 const float* __restrict__ bboxes,
                 float* __restrict__ iou_out)
{
    __shared__ float bx1[NBOX], by1[NBOX], bx2[NBOX], by2[NBOX], ga[NBOX];
    const int b = blockIdx.z;
    const int a = blockIdx.y;
    const int tid  = threadIdx.x;
    const int wid  = tid >> 5;
    const int lane = tid & 31;

    if (tid < NBOX) {
        const float* bb = bboxes + ((size_t)b * NBOX + tid) * 5;
        float x1 = bb[0], y1 = bb[1], x2 = bb[2], y2 = bb[3];
        bx1[tid] = x1; by1[tid] = y1; bx2[tid] = x2; by2[tid] = y2;
        ga[tid] = (x2 - x1) * (y2 - y1);
    }
    __syncthreads();

    const float wa = anc[a * 2 + 0], ha = anc[a * 2 + 1];
    const float* o = g_out2 + (size_t)b * OUTCH * HW;
    const int pBase = blockIdx.x * 128 + wid * 16;

    for (int q = 0; q < 16; q++) {
        int p = pBase + q;
        if (p >= HW) break;
        float tx = o[(5 * a + 1) * HW + p];
        float ty = o[(5 * a + 2) * HW + p];
        float tw = o[(5 * a + 3) * HW + p];
        float th = o[(5 * a + 4) * HW + p];
        int h = p / WW, w = p % WW;
        float cx = (w + 0.5f) + tx;
        float cy = (h + 0.5f) + ty;
        float nw = wa * expf(tw);
        float nh = ha * expf(th);
        float px1 = cx - nw * 0.5f, px2 = cx + nw * 0.5f;
        float py1 = cy - nh * 0.5f, py2 = cy + nh * 0.5f;
        float parea = (px2 - px1) * (py2 - py1);

        float* orow = iou_out + (((size_t)b * A_NUM + a) * HW + p) * NBOX;
        #pragma unroll
        for (int gg = 0; gg < 2; gg++) {
            int gi = lane + gg * 32;
            float ix1 = fmaxf(px1, bx1[gi]);
            float iy1 = fmaxf(py1, by1[gi]);
            float ix2 = fminf(px2, bx2[gi]);
            float iy2 = fminf(py2, by2[gi]);
            float inter = fmaxf(ix2 - ix1, 0.f) * fmaxf(iy2 - iy1, 0.f);
            orow[gi] = inter / (ga[gi] + parea - inter);
        }
    }
}

// ---------------------------------------------------------------------------
__global__ __launch_bounds__(64)
void loss_part(const int* __restrict__ pos_idx,
               const int* __restrict__ neg_idx,
               const float* __restrict__ gt_off)
{
    __shared__ float red[64];
    const int tid = threadIdx.x;
    const int m   = blockIdx.x * 64 + tid;
    float s = 0.f;
    {
        int idx = pos_idx[m];
        int b   = idx / (A_NUM * HW);
        int rem = idx % (A_NUM * HW);
        int a   = rem / HW;
        int p   = rem % HW;
        const float* o = g_out2 + ((size_t)b * OUTCH + 5 * a) * HW + p;
        float c  = o[0];
        float sc = 1.f / (1.f + expf(-c));
        float d  = sc - 1.f;
        s += 0.5f * d * d;
        #pragma unroll
        for (int k = 0; k < 4; k++) {
            float dd = o[(size_t)(1 + k) * HW] - gt_off[m * 4 + k];
            s += dd * dd;
        }
        int nidx = neg_idx[m];
        int nb   = nidx / (A_NUM * HW);
        int nrem = nidx % (A_NUM * HW);
        int na   = nrem / HW;
        int np   = nrem % HW;
        float nc = g_out2[((size_t)nb * OUTCH + 5 * na) * HW + np];
        float nsc = 1.f / (1.f + expf(-nc));
        s += 0.5f * nsc * nsc;
    }
    red[tid] = s;
    __syncthreads();
    for (int st = 32; st > 0; st >>= 1) {
        if (tid < st) red[tid] += red[tid + st];
        __syncthreads();
    }
    if (tid == 0) g_loss_part[blockIdx.x] = red[0];
}

__global__ void loss_final(float* __restrict__ out0)
{
    float s = 0.f;
    #pragma unroll
    for (int i = 0; i < 32; i++) s += g_loss_part[i];
    out0[0] = s / (float)MPOS;
}

// ---------------------------------------------------------------------------
__global__ __launch_bounds__(256)
void class_kernel(const int* __restrict__ pos_idx,
                  float* __restrict__ out_cls)
{
    int t = blockIdx.x * blockDim.x + threadIdx.x;
    if (t >= MPOS * C_NUM) return;
    int m = t / C_NUM;
    int c = t % C_NUM;
    int idx = pos_idx[m];
    int b = idx / (A_NUM * HW);
    int p = idx % HW;
    out_cls[t] = g_out2[((size_t)b * OUTCH + 5 * A_NUM + c) * HW + p];
}

// ---------------------------------------------------------------------------
extern "C" void kernel_launch(void* const* d_in, const int* in_sizes, int n_in,
                              void* d_out, int out_size)
{
    const float* features = (const float*)d_in[0];
    const float* w1       = (const float*)d_in[1];
    const float* b1       = (const float*)d_in[2];
    const float* w2       = (const float*)d_in[3];
    const float* b2       = (const float*)d_in[4];
    const float* anc      = (const float*)d_in[5];
    const float* bboxes   = (const float*)d_in[7];
    const float* gt_off   = (const float*)d_in[8];
    const int*   pos_idx  = (const int*)d_in[9];
    const int*   neg_idx  = (const int*)d_in[10];

    float* out      = (float*)d_out;
    float* loss_out = out;
    float* iou_out  = out + 1;
    float* cls_out  = out + 1 + (size_t)BATCH * A_NUM * HW * NBOX;

    // stage sizes: G1 = 2*256*80 + 64*272 = 58368; G2 = 2*128*80 + 64*528 = 54272
    const int SMEM1 = 2 * 58368;
    const int SMEM2 = 2 * 54272;
    cudaFuncSetAttribute((const void*)gemm_pipe<256, 128, KDIM, true>,
                         cudaFuncAttributeMaxDynamicSharedMemorySize, SMEM1);
    cudaFuncSetAttribute((const void*)gemm_pipe<128, 256, OUTCH, false>,
                         cudaFuncAttributeMaxDynamicSharedMemorySize, SMEM2);

    __nv_bfloat16 *w1h, *w1l, *w2h, *w2l, *fh, *fl, *hh, *hl;
    cudaGetSymbolAddress((void**)&w1h, g_w1_hi);
    cudaGetSymbolAddress((void**)&w1l, g_w1_lo);
    cudaGetSymbolAddress((void**)&w2h, g_w2_hi);
    cudaGetSymbolAddress((void**)&w2l, g_w2_lo);
    cudaGetSymbolAddress((void**)&fh,  g_feat_hi);
    cudaGetSymbolAddress((void**)&fl,  g_feat_lo);
    cudaGetSymbolAddress((void**)&hh,  g_hid_hi);
    cudaGetSymbolAddress((void**)&hl,  g_hid_lo);

    convert_split<<<(KDIM * KDIM / 4 + 255) / 256, 256>>>(w1, w1h, w1l, KDIM * KDIM / 4);
    convert_split<<<(OUTCH * KDIM / 4 + 255) / 256, 256>>>(w2, w2h, w2l, OUTCH * KDIM / 4);
    {
        int n4 = (int)((size_t)BATCH * KDIM * HW / 4);
        convert_split<<<(n4 + 255) / 256, 256>>>(features, fh, fl, n4);
    }

    gemm_pipe<256, 128, KDIM, true><<<dim3(25, 1, BATCH), 256, SMEM1>>>(w1h, w1l, fh, fl, b1);
    gemm_pipe<128, 256, OUTCH, false><<<dim3(13, 1, BATCH), 256, SMEM2>>>(w2h, w2l, hh, hl, b2);

    head_kernel<<<dim3(25, A_NUM, BATCH), 256>>>(anc, bboxes, iou_out);
    loss_part<<<32, 64>>>(pos_idx, neg_idx, gt_off);
    loss_final<<<1, 1>>>(loss_out);
    class_kernel<<<(MPOS * C_NUM + 255) / 256, 256>>>(pos_idx, cls_out);
}

// round 11
// speedup vs baseline: 1.0873x; 1.0873x over previous
#include <cuda_runtime.h>
#include <cuda_bf16.h>
#include <math.h>
#include <stdint.h>

#define A_NUM   9
#define C_NUM   20
#define OUTCH   65
#define BATCH   32
#define KDIM    256
#define HH      56
#define WW      56
#define HW      3136
#define NBOX    64
#define MPOS    2048

// ---- global scratch ----
__device__ __nv_bfloat16 g_w1_hi[KDIM * KDIM];
__device__ __nv_bfloat16 g_w1_lo[KDIM * KDIM];
__device__ __nv_bfloat16 g_w2_hi[OUTCH * KDIM];
__device__ __nv_bfloat16 g_w2_lo[OUTCH * KDIM];
__device__ __nv_bfloat16 g_feat_hi[(size_t)BATCH * KDIM * HW];
__device__ __nv_bfloat16 g_feat_lo[(size_t)BATCH * KDIM * HW];
__device__ __nv_bfloat16 g_hid_hi[(size_t)BATCH * KDIM * HW];   // [b][m][p]
__device__ __nv_bfloat16 g_hid_lo[(size_t)BATCH * KDIM * HW];
__device__ float         g_out2 [(size_t)BATCH * OUTCH * HW];   // [b][m][p]
__device__ float         g_loss_part[32];

// ---- helpers ----
__device__ __forceinline__ uint32_t smem_u32(const void* p) {
    uint32_t a;
    asm("{ .reg .u64 t; cvta.to.shared.u64 t, %1; cvt.u32.u64 %0, t; }"
        : "=r"(a) : "l"(p));
    return a;
}
__device__ __forceinline__ uint32_t pk2(__nv_bfloat16 a, __nv_bfloat16 b) {
    __nv_bfloat162 t; t.x = a; t.y = b;
    return *(uint32_t*)&t;
}
__device__ __forceinline__ void split1(float x, __nv_bfloat16& h, __nv_bfloat16& l) {
    h = __float2bfloat16(x);
    l = __float2bfloat16(x - __bfloat162float(h));
}
__device__ __forceinline__ void mma16816(float* c,
    const uint32_t* a, uint32_t b0, uint32_t b1)
{
    asm volatile(
        "mma.sync.aligned.m16n8k16.row.col.f32.bf16.bf16.f32 "
        "{%0,%1,%2,%3}, {%4,%5,%6,%7}, {%8,%9}, {%0,%1,%2,%3};"
        : "+f"(c[0]), "+f"(c[1]), "+f"(c[2]), "+f"(c[3])
        : "r"(a[0]), "r"(a[1]), "r"(a[2]), "r"(a[3]), "r"(b0), "r"(b1));
}
__device__ __forceinline__ void ldmx4(uint32_t* r, uint32_t addr) {
    asm volatile("ldmatrix.sync.aligned.m8n8.x4.shared.b16 {%0,%1,%2,%3}, [%4];"
        : "=r"(r[0]), "=r"(r[1]), "=r"(r[2]), "=r"(r[3]) : "r"(addr));
}
__device__ __forceinline__ void ldmx4t(uint32_t* r, uint32_t addr) {
    asm volatile("ldmatrix.sync.aligned.m8n8.x4.trans.shared.b16 {%0,%1,%2,%3}, [%4];"
        : "=r"(r[0]), "=r"(r[1]), "=r"(r[2]), "=r"(r[3]) : "r"(addr));
}
__device__ __forceinline__ void cpa16(uint32_t dst, const void* src, bool ok) {
    uint32_t sz = ok ? 16u : 0u;
    asm volatile("cp.async.cg.shared.global [%0], [%1], 16, %2;"
                 :: "r"(dst), "l"(src), "r"(sz));
}
__device__ __forceinline__ void cpa_commit() {
    asm volatile("cp.async.commit_group;" ::: "memory");
}
__device__ __forceinline__ void cpa_wait1() {
    asm volatile("cp.async.wait_group 1;" ::: "memory");
}

// ---- SMEM: BK=32. A [m128][k32] pitch 80B; B [k32][p128] pitch 272B.
#define APITCH  80
#define BPITCH  272
#define AHI_OFF 0
#define ALO_OFF 10240
#define BHI_OFF 20480
#define BLO_OFF 29184
#define STAGE   37888
#define NSTAGE  3
#define GEMM_SMEM (STAGE * NSTAGE)     // 113664; 2 CTAs = 222KB <= 228KB smem

// ---------------------------------------------------------------------------
__global__ __launch_bounds__(256)
void convert_split(const float* __restrict__ src,
                   __nv_bfloat16* __restrict__ hi,
                   __nv_bfloat16* __restrict__ lo, int n4)
{
    int t = blockIdx.x * blockDim.x + threadIdx.x;
    if (t >= n4) return;
    float4 v = ((const float4*)src)[t];
    __nv_bfloat16 h0, h1, h2, h3, l0, l1, l2, l3;
    split1(v.x, h0, l0); split1(v.y, h1, l1);
    split1(v.z, h2, l2); split1(v.w, h3, l3);
    ((uint2*)hi)[t] = make_uint2(pk2(h0, h1), pk2(h2, h3));
    ((uint2*)lo)[t] = make_uint2(pk2(l0, l1), pk2(l2, l3));
}

// ---------------------------------------------------------------------------
// Pipelined split-bf16 HMMA GEMM. Block tile 128m x 128p, 8 warps (2m x 4n),
// warp tile 64x32, BK=32, 3-stage cp.async, 2 CTAs/SM, ONE barrier per chunk.
// Order: wait1 -> sync -> issue(c+2) -> commit -> compute(c).
// (cp.async groups are per-thread; the barrier AFTER the wait publishes all
//  threads' copies. issue targets (c+2)%3 whose readers finished at c-1,
//  which is before this barrier -> WAR safe.)
// ---------------------------------------------------------------------------
template<int MROWS, bool FIRST>
__global__ __launch_bounds__(256, 2)
void gemm_pipe(const __nv_bfloat16* __restrict__ Ahi_g,
               const __nv_bfloat16* __restrict__ Alo_g,
               const __nv_bfloat16* __restrict__ Bhi_g,
               const __nv_bfloat16* __restrict__ Blo_g,
               const float* __restrict__ bias)
{
    extern __shared__ char smem[];
    const uint32_t sb = smem_u32(smem);

    const int b     = blockIdx.z;
    const int mBase = blockIdx.y * 128;
    const int nBase = blockIdx.x * 128;        // 25 tiles, last is partial
    const int tid   = threadIdx.x;
    const int wid   = tid >> 5;
    const int lane  = tid & 31;
    const int wm    = wid >> 2;                // 0..1 (m offset wm*64)
    const int wn    = wid & 3;                 // 0..3 (n offset wn*32)

    const size_t bofs = (size_t)b * KDIM * HW;

    float acc[4][4][4];
    #pragma unroll
    for (int i = 0; i < 4; i++)
        #pragma unroll
        for (int j = 0; j < 4; j++)
            #pragma unroll
            for (int q = 0; q < 4; q++) acc[i][j][q] = 0.f;

    // per-thread loader coordinates
    const int aR0 = tid >> 2;                  // 0..63
    const int aC  = tid & 3;
    const bool aOk0 = (mBase + aR0) < MROWS;
    const bool aOk1 = (mBase + aR0 + 64) < MROWS;
    const int bR0 = tid >> 4;                  // 0..15
    const int bC  = tid & 15;
    const int bP  = nBase + bC * 8;
    const bool bOk = bP < HW;

    const __nv_bfloat16* aH0 = Ahi_g + (aOk0 ? ((size_t)(mBase + aR0) * KDIM + aC * 8) : 0);
    const __nv_bfloat16* aL0 = Alo_g + (aOk0 ? ((size_t)(mBase + aR0) * KDIM + aC * 8) : 0);
    const __nv_bfloat16* aH1 = Ahi_g + (aOk1 ? ((size_t)(mBase + aR0 + 64) * KDIM + aC * 8) : 0);
    const __nv_bfloat16* aL1 = Alo_g + (aOk1 ? ((size_t)(mBase + aR0 + 64) * KDIM + aC * 8) : 0);
    const __nv_bfloat16* bH0 = Bhi_g + bofs + (size_t)bR0 * HW + bP;
    const __nv_bfloat16* bL0 = Blo_g + bofs + (size_t)bR0 * HW + bP;
    const uint32_t aD0 = aR0 * APITCH + aC * 16;
    const uint32_t aD1 = (aR0 + 64) * APITCH + aC * 16;
    const uint32_t bD0 = bR0 * BPITCH + bC * 16;
    const uint32_t bD1 = (bR0 + 16) * BPITCH + bC * 16;

    #define ISSUE_CHUNK(ST, KO)                                                  \
        do {                                                                     \
            cpa16((ST) + AHI_OFF + aD0, aH0 + (KO), aOk0);                       \
            cpa16((ST) + AHI_OFF + aD1, aH1 + (KO), aOk1);                       \
            cpa16((ST) + ALO_OFF + aD0, aL0 + (KO), aOk0);                       \
            cpa16((ST) + ALO_OFF + aD1, aL1 + (KO), aOk1);                       \
            cpa16((ST) + BHI_OFF + bD0, bH0 + (size_t)(KO) * HW, bOk);           \
            cpa16((ST) + BHI_OFF + bD1, bH0 + (size_t)((KO) + 16) * HW, bOk);    \
            cpa16((ST) + BLO_OFF + bD0, bL0 + (size_t)(KO) * HW, bOk);           \
            cpa16((ST) + BLO_OFF + bD1, bL0 + (size_t)((KO) + 16) * HW, bOk);    \
        } while (0)

    // prologue: chunks 0,1
    ISSUE_CHUNK(sb, 0);
    cpa_commit();
    ISSUE_CHUNK(sb + STAGE, 32);
    cpa_commit();

    // warp-uniform m-frag validity (prunes GEMM2 padding work)
    bool vi[4];
    #pragma unroll
    for (int i = 0; i < 4; i++)
        vi[i] = FIRST ? true : ((mBase + wm * 64 + i * 16) < MROWS);
    // warp-uniform n validity (prunes tail n-tile work)
    const bool vj = (nBase + wn * 32) < HW;

    const int lane15 = lane & 15;
    const int laneHi = lane >> 4;
    const int kB     = (lane >> 3) & 1;
    const int lane7  = lane & 7;
    const uint32_t aFragBase = (wm * 64 + lane15) * APITCH + laneHi * 16;
    const uint32_t bFragRow  = kB * 8 + lane7;
    const uint32_t bFragCol  = (wn * 32 + laneHi * 8) * 2;

    #pragma unroll 1
    for (int c = 0; c < 8; c++) {
        cpa_wait1();          // own groups: all but newest done -> chunk c resident
        __syncthreads();      // publish chunk c; orders compute(c-1) before refill
        if (c + 2 < 8) {
            const uint32_t st2 = sb + ((c + 2) % NSTAGE) * STAGE;
            const int ko = (c + 2) * 32;
            ISSUE_CHUNK(st2, ko);
        }
        cpa_commit();
        const uint32_t st = sb + (c % NSTAGE) * STAGE;

        if (vj) {
            #pragma unroll
            for (int ks = 0; ks < 2; ks++) {
                uint32_t ah[4][4], bh[4][2];
                #pragma unroll
                for (int i = 0; i < 4; i++)
                    if (vi[i])
                        ldmx4(ah[i], st + AHI_OFF + aFragBase + i * 16 * APITCH + ks * 32);
                {
                    uint32_t r[4];
                    ldmx4t(r, st + BHI_OFF + (ks * 16 + bFragRow) * BPITCH + bFragCol);
                    bh[0][0] = r[0]; bh[0][1] = r[1]; bh[1][0] = r[2]; bh[1][1] = r[3];
                    ldmx4t(r, st + BHI_OFF + (ks * 16 + bFragRow) * BPITCH + bFragCol + 32);
                    bh[2][0] = r[0]; bh[2][1] = r[1]; bh[3][0] = r[2]; bh[3][1] = r[3];
                }
                #pragma unroll
                for (int i = 0; i < 4; i++)
                    if (vi[i])
                        #pragma unroll
                        for (int j = 0; j < 4; j++)
                            mma16816(acc[i][j], ah[i], bh[j][0], bh[j][1]);
                {
                    uint32_t bl[4][2], r[4];
                    ldmx4t(r, st + BLO_OFF + (ks * 16 + bFragRow) * BPITCH + bFragCol);
                    bl[0][0] = r[0]; bl[0][1] = r[1]; bl[1][0] = r[2]; bl[1][1] = r[3];
                    ldmx4t(r, st + BLO_OFF + (ks * 16 + bFragRow) * BPITCH + bFragCol + 32);
                    bl[2][0] = r[0]; bl[2][1] = r[1]; bl[3][0] = r[2]; bl[3][1] = r[3];
                    #pragma unroll
                    for (int i = 0; i < 4; i++)
                        if (vi[i])
                            #pragma unroll
                            for (int j = 0; j < 4; j++)
                                mma16816(acc[i][j], ah[i], bl[j][0], bl[j][1]);
                }
                {
                    uint32_t al[4];
                    #pragma unroll
                    for (int i = 0; i < 4; i++)
                        if (vi[i]) {
                            ldmx4(al, st + ALO_OFF + aFragBase + i * 16 * APITCH + ks * 32);
                            #pragma unroll
                            for (int j = 0; j < 4; j++)
                                mma16816(acc[i][j], al, bh[j][0], bh[j][1]);
                        }
                }
            }
        }
    }
    #undef ISSUE_CHUNK

    // ---- epilogue ----
    const int g   = lane >> 2;
    const int tig = lane & 3;
    #pragma unroll
    for (int i = 0; i < 4; i++) {
        const int m0 = mBase + wm * 64 + i * 16 + g;
        if (FIRST) {
            const float bv0 = bias[m0];
            const float bv1 = bias[m0 + 8];
            #pragma unroll
            for (int j = 0; j < 4; j++) {
                int p = nBase + wn * 32 + j * 8 + tig * 2;
                if (p < HW) {
                    float f0 = acc[i][j][0] + bv0; f0 = f0 >= 0.f ? f0 : 0.01f * f0;
                    float f1 = acc[i][j][1] + bv0; f1 = f1 >= 0.f ? f1 : 0.01f * f1;
                    float f2 = acc[i][j][2] + bv1; f2 = f2 >= 0.f ? f2 : 0.01f * f2;
                    float f3 = acc[i][j][3] + bv1; f3 = f3 >= 0.f ? f3 : 0.01f * f3;
                    __nv_bfloat16 h0, h1, h2, h3, l0, l1, l2, l3;
                    split1(f0, h0, l0); split1(f1, h1, l1);
                    split1(f2, h2, l2); split1(f3, h3, l3);
                    size_t o0 = bofs + (size_t)m0 * HW + p;
                    size_t o1 = bofs + (size_t)(m0 + 8) * HW + p;
                    *(uint32_t*)&g_hid_hi[o0] = pk2(h0, h1);
                    *(uint32_t*)&g_hid_lo[o0] = pk2(l0, l1);
                    *(uint32_t*)&g_hid_hi[o1] = pk2(h2, h3);
                    *(uint32_t*)&g_hid_lo[o1] = pk2(l2, l3);
                }
            }
        } else {
            const bool ok0 = m0 < MROWS;
            const bool ok1 = (m0 + 8) < MROWS;
            if (!ok0 && !ok1) continue;
            const float bv0 = ok0 ? bias[m0] : 0.f;
            const float bv1 = ok1 ? bias[m0 + 8] : 0.f;
            #pragma unroll
            for (int j = 0; j < 4; j++) {
                int p = nBase + wn * 32 + j * 8 + tig * 2;
                if (p < HW) {
                    if (ok0) {
                        float2 v = make_float2(acc[i][j][0] + bv0, acc[i][j][1] + bv0);
                        *(float2*)&g_out2[((size_t)b * OUTCH + m0) * HW + p] = v;
                    }
                    if (ok1) {
                        float2 v = make_float2(acc[i][j][2] + bv1, acc[i][j][3] + bv1);
                        *(float2*)&g_out2[((size_t)b * OUTCH + m0 + 8) * HW + p] = v;
                    }
                }
            }
        }
    }
}

// ---------------------------------------------------------------------------
__global__ __launch_bounds__(256)
void head_kernel(const float* __restrict__ anc,
                 const float* __restrict__ bboxes,
                 float* __restrict__ iou_out)
{
    __shared__ float bx1[NBOX], by1[NBOX], bx2[NBOX], by2[NBOX], ga[NBOX];
    const int b = blockIdx.z;
    const int a = blockIdx.y;
    const int tid  = threadIdx.x;
    const int wid  = tid >> 5;
    const int lane = tid & 31;

    if (tid < NBOX) {
        const float* bb = bboxes + ((size_t)b * NBOX + tid) * 5;
        float x1 = bb[0], y1 = bb[1], x2 = bb[2], y2 = bb[3];
        bx1[tid] = x1; by1[tid] = y1; bx2[tid] = x2; by2[tid] = y2;
        ga[tid] = (x2 - x1) * (y2 - y1);
    }
    __syncthreads();

    const float wa = anc[a * 2 + 0], ha = anc[a * 2 + 1];
    const float* o = g_out2 + (size_t)b * OUTCH * HW;
    const int pBase = blockIdx.x * 128 + wid * 16;

    for (int q = 0; q < 16; q++) {
        int p = pBase + q;
        if (p >= HW) break;
        float tx = o[(5 * a + 1) * HW + p];
        float ty = o[(5 * a + 2) * HW + p];
        float tw = o[(5 * a + 3) * HW + p];
        float th = o[(5 * a + 4) * HW + p];
        int h = p / WW, w = p % WW;
        float cx = (w + 0.5f) + tx;
        float cy = (h + 0.5f) + ty;
        float nw = wa * expf(tw);
        float nh = ha * expf(th);
        float px1 = cx - nw * 0.5f, px2 = cx + nw * 0.5f;
        float py1 = cy - nh * 0.5f, py2 = cy + nh * 0.5f;
        float parea = (px2 - px1) * (py2 - py1);

        float* orow = iou_out + (((size_t)b * A_NUM + a) * HW + p) * NBOX;
        #pragma unroll
        for (int gg = 0; gg < 2; gg++) {
            int gi = lane + gg * 32;
            float ix1 = fmaxf(px1, bx1[gi]);
            float iy1 = fmaxf(py1, by1[gi]);
            float ix2 = fminf(px2, bx2[gi]);
            float iy2 = fminf(py2, by2[gi]);
            float inter = fmaxf(ix2 - ix1, 0.f) * fmaxf(iy2 - iy1, 0.f);
            orow[gi] = inter / (ga[gi] + parea - inter);
        }
    }
}

// ---------------------------------------------------------------------------
__global__ __launch_bounds__(64)
void loss_part(const int* __restrict__ pos_idx,
               const int* __restrict__ neg_idx,
               const float* __restrict__ gt_off)
{
    __shared__ float red[64];
    const int tid = threadIdx.x;
    const int m   = blockIdx.x * 64 + tid;
    float s = 0.f;
    {
        int idx = pos_idx[m];
        int b   = idx / (A_NUM * HW);
        int rem = idx % (A_NUM * HW);
        int a   = rem / HW;
        int p   = rem % HW;
        const float* o = g_out2 + ((size_t)b * OUTCH + 5 * a) * HW + p;
        float c  = o[0];
        float sc = 1.f / (1.f + expf(-c));
        float d  = sc - 1.f;
        s += 0.5f * d * d;
        #pragma unroll
        for (int k = 0; k < 4; k++) {
            float dd = o[(size_t)(1 + k) * HW] - gt_off[m * 4 + k];
            s += dd * dd;
        }
        int nidx = neg_idx[m];
        int nb   = nidx / (A_NUM * HW);
        int nrem = nidx % (A_NUM * HW);
        int na   = nrem / HW;
        int np   = nrem % HW;
        float nc = g_out2[((size_t)nb * OUTCH + 5 * na) * HW + np];
        float nsc = 1.f / (1.f + expf(-nc));
        s += 0.5f * nsc * nsc;
    }
    red[tid] = s;
    __syncthreads();
    for (int st = 32; st > 0; st >>= 1) {
        if (tid < st) red[tid] += red[tid + st];
        __syncthreads();
    }
    if (tid == 0) g_loss_part[blockIdx.x] = red[0];
}

__global__ void loss_final(float* __restrict__ out0)
{
    float s = 0.f;
    #pragma unroll
    for (int i = 0; i < 32; i++) s += g_loss_part[i];
    out0[0] = s / (float)MPOS;
}

// ---------------------------------------------------------------------------
__global__ __launch_bounds__(256)
void class_kernel(const int* __restrict__ pos_idx,
                  float* __restrict__ out_cls)
{
    int t = blockIdx.x * blockDim.x + threadIdx.x;
    if (t >= MPOS * C_NUM) return;
    int m = t / C_NUM;
    int c = t % C_NUM;
    int idx = pos_idx[m];
    int b = idx / (A_NUM * HW);
    int p = idx % HW;
    out_cls[t] = g_out2[((size_t)b * OUTCH + 5 * A_NUM + c) * HW + p];
}

// ---------------------------------------------------------------------------
extern "C" void kernel_launch(void* const* d_in, const int* in_sizes, int n_in,
                              void* d_out, int out_size)
{
    const float* features = (const float*)d_in[0];
    const float* w1       = (const float*)d_in[1];
    const float* b1       = (const float*)d_in[2];
    const float* w2       = (const float*)d_in[3];
    const float* b2       = (const float*)d_in[4];
    const float* anc      = (const float*)d_in[5];
    const float* bboxes   = (const float*)d_in[7];
    const float* gt_off   = (const float*)d_in[8];
    const int*   pos_idx  = (const int*)d_in[9];
    const int*   neg_idx  = (const int*)d_in[10];

    float* out      = (float*)d_out;
    float* loss_out = out;
    float* iou_out  = out + 1;
    float* cls_out  = out + 1 + (size_t)BATCH * A_NUM * HW * NBOX;

    cudaFuncSetAttribute(gemm_pipe<KDIM, true>,
                         cudaFuncAttributeMaxDynamicSharedMemorySize, GEMM_SMEM);
    cudaFuncSetAttribute(gemm_pipe<OUTCH, false>,
                         cudaFuncAttributeMaxDynamicSharedMemorySize, GEMM_SMEM);

    __nv_bfloat16 *w1h, *w1l, *w2h, *w2l, *fh, *fl, *hh, *hl;
    cudaGetSymbolAddress((void**)&w1h, g_w1_hi);
    cudaGetSymbolAddress((void**)&w1l, g_w1_lo);
    cudaGetSymbolAddress((void**)&w2h, g_w2_hi);
    cudaGetSymbolAddress((void**)&w2l, g_w2_lo);
    cudaGetSymbolAddress((void**)&fh,  g_feat_hi);
    cudaGetSymbolAddress((void**)&fl,  g_feat_lo);
    cudaGetSymbolAddress((void**)&hh,  g_hid_hi);
    cudaGetSymbolAddress((void**)&hl,  g_hid_lo);

    convert_split<<<(KDIM * KDIM / 4 + 255) / 256, 256>>>(w1, w1h, w1l, KDIM * KDIM / 4);
    convert_split<<<(OUTCH * KDIM / 4 + 255) / 256, 256>>>(w2, w2h, w2l, OUTCH * KDIM / 4);
    {
        int n4 = (int)((size_t)BATCH * KDIM * HW / 4);
        convert_split<<<(n4 + 255) / 256, 256>>>(features, fh, fl, n4);
    }

    gemm_pipe<KDIM, true><<<dim3(25, 2, BATCH), 256, GEMM_SMEM>>>(w1h, w1l, fh, fl, b1);
    gemm_pipe<OUTCH, false><<<dim3(25, 1, BATCH), 256, GEMM_SMEM>>>(w2h, w2l, hh, hl, b2);

    head_kernel<<<dim3(25, A_NUM, BATCH), 256>>>(anc, bboxes, iou_out);
    loss_part<<<32, 64>>>(pos_idx, neg_idx, gt_off);
    loss_final<<<1, 1>>>(loss_out);
    class_kernel<<<(MPOS * C_NUM + 255) / 256, 256>>>(pos_idx, cls_out);
}

// round 12
// speedup vs baseline: 1.1148x; 1.0253x over previous
#include <cuda_runtime.h>
#include <cuda_bf16.h>
#include <math.h>
#include <stdint.h>

#define A_NUM   9
#define C_NUM   20
#define OUTCH   65
#define BATCH   32
#define KDIM    256
#define HH      56
#define WW      56
#define HW      3136
#define NBOX    64
#define MPOS    2048

// ---- global scratch ----
__device__ __nv_bfloat16 g_w1_hi[KDIM * KDIM];
__device__ __nv_bfloat16 g_w1_lo[KDIM * KDIM];
__device__ __nv_bfloat16 g_w2_hi[OUTCH * KDIM];
__device__ __nv_bfloat16 g_w2_lo[OUTCH * KDIM];
__device__ __nv_bfloat16 g_feat_hi[(size_t)BATCH * KDIM * HW];
__device__ __nv_bfloat16 g_feat_lo[(size_t)BATCH * KDIM * HW];
__device__ float         g_out2 [(size_t)BATCH * OUTCH * HW];   // [b][m][p]
__device__ float         g_loss_part[32];

// ---- helpers ----
__device__ __forceinline__ uint32_t smem_u32(const void* p) {
    uint32_t a;
    asm("{ .reg .u64 t; cvta.to.shared.u64 t, %1; cvt.u32.u64 %0, t; }"
        : "=r"(a) : "l"(p));
    return a;
}
__device__ __forceinline__ uint32_t pk2(__nv_bfloat16 a, __nv_bfloat16 b) {
    __nv_bfloat162 t; t.x = a; t.y = b;
    return *(uint32_t*)&t;
}
__device__ __forceinline__ void split1(float x, __nv_bfloat16& h, __nv_bfloat16& l) {
    h = __float2bfloat16(x);
    l = __float2bfloat16(x - __bfloat162float(h));
}
__device__ __forceinline__ void mma16816(float* c,
    const uint32_t* a, uint32_t b0, uint32_t b1)
{
    asm volatile(
        "mma.sync.aligned.m16n8k16.row.col.f32.bf16.bf16.f32 "
        "{%0,%1,%2,%3}, {%4,%5,%6,%7}, {%8,%9}, {%0,%1,%2,%3};"
        : "+f"(c[0]), "+f"(c[1]), "+f"(c[2]), "+f"(c[3])
        : "r"(a[0]), "r"(a[1]), "r"(a[2]), "r"(a[3]), "r"(b0), "r"(b1));
}
__device__ __forceinline__ void ldmx4(uint32_t* r, uint32_t addr) {
    asm volatile("ldmatrix.sync.aligned.m8n8.x4.shared.b16 {%0,%1,%2,%3}, [%4];"
        : "=r"(r[0]), "=r"(r[1]), "=r"(r[2]), "=r"(r[3]) : "r"(addr));
}
__device__ __forceinline__ void ldmx4t(uint32_t* r, uint32_t addr) {
    asm volatile("ldmatrix.sync.aligned.m8n8.x4.trans.shared.b16 {%0,%1,%2,%3}, [%4];"
        : "=r"(r[0]), "=r"(r[1]), "=r"(r[2]), "=r"(r[3]) : "r"(addr));
}
__device__ __forceinline__ void ldmx2t(uint32_t& r0, uint32_t& r1, uint32_t addr) {
    asm volatile("ldmatrix.sync.aligned.m8n8.x2.trans.shared.b16 {%0,%1}, [%2];"
        : "=r"(r0), "=r"(r1) : "r"(addr));
}
__device__ __forceinline__ void cpa16(uint32_t dst, const void* src, bool ok) {
    uint32_t sz = ok ? 16u : 0u;
    asm volatile("cp.async.cg.shared.global [%0], [%1], 16, %2;"
                 :: "r"(dst), "l"(src), "r"(sz));
}
__device__ __forceinline__ void cpa_commit() {
    asm volatile("cp.async.commit_group;" ::: "memory");
}
__device__ __forceinline__ void cpa_wait1() {
    asm volatile("cp.async.wait_group 1;" ::: "memory");
}
__device__ __forceinline__ void cpa_wait0() {
    asm volatile("cp.async.wait_group 0;" ::: "memory");
}

// ---- SMEM layout ----
// Phase 1 (2 stages): A [256m][k32] pitch 80B (hi+lo), B [k32][64p] pitch 144B (hi+lo)
#define APITCH   80
#define BPITCH   144
#define AHI_OFF  0
#define ALO_OFF  20480
#define BHI_OFF  40960
#define BLO_OFF  45568
#define STAGE    50176
// Phase 2 (reuses same region): hidden [k256][64p] pitch 144 (hi at 0, lo at 36864),
// W2 chunk buffers [80m][k32] pitch 80 at 73728+st*12800 (hi +0, lo +6400)
#define HIDHI    0
#define HIDLO    36864
#define W2BASE   73728
#define W2STG    12800
#define GEMM_SMEM 100352     // 2 CTAs/SM (200.7KB of 228KB)

// ---------------------------------------------------------------------------
__global__ __launch_bounds__(256)
void convert_split(const float* __restrict__ src,
                   __nv_bfloat16* __restrict__ hi,
                   __nv_bfloat16* __restrict__ lo, int n4)
{
    int t = blockIdx.x * blockDim.x + threadIdx.x;
    if (t >= n4) return;
    float4 v = ((const float4*)src)[t];
    __nv_bfloat16 h0, h1, h2, h3, l0, l1, l2, l3;
    split1(v.x, h0, l0); split1(v.y, h1, l1);
    split1(v.z, h2, l2); split1(v.w, h3, l3);
    ((uint2*)hi)[t] = make_uint2(pk2(h0, h1), pk2(h2, h3));
    ((uint2*)lo)[t] = make_uint2(pk2(l0, l1), pk2(l2, l3));
}

// ---------------------------------------------------------------------------
// Fused conv1+conv2. Block: 256m x 64p (grid 49 x 32 exact, no p guards).
// Phase 1: hidden = leaky(W1 @ F + b1) -> kept in SMEM (split bf16, B-layout).
// Phase 2: out2 = W2 @ hidden + b2 -> g_out2. Hidden never touches HBM.
// Pipeline ordering per chunk (R9-proven): wait1 -> sync -> compute -> sync ->
// issue(c+2) -> commit. (cp.async groups are per-thread; the barrier after the
// wait publishes all threads' copies; the barrier before issue protects WAR.)
// ---------------------------------------------------------------------------
__global__ __launch_bounds__(256, 2)
void gemm_fused(const __nv_bfloat16* __restrict__ Ahi_g,
                const __nv_bfloat16* __restrict__ Alo_g,
                const __nv_bfloat16* __restrict__ Bhi_g,
                const __nv_bfloat16* __restrict__ Blo_g,
                const float* __restrict__ bias1,
                const __nv_bfloat16* __restrict__ W2hi_g,
                const __nv_bfloat16* __restrict__ W2lo_g,
                const float* __restrict__ bias2)
{
    extern __shared__ char smem[];
    const uint32_t sb = smem_u32(smem);

    const int b     = blockIdx.z;
    const int nBase = blockIdx.x * 64;         // 49*64 = 3136 exact
    const int tid   = threadIdx.x;
    const int wid   = tid >> 5;
    const int lane  = tid & 31;
    const int wm    = wid >> 1;                // 0..3 (m offset wm*64)
    const int wn    = wid & 1;                 // 0..1 (p offset wn*32)

    const size_t bofs = (size_t)b * KDIM * HW;

    // ---- phase-1 loader coordinates (no bounds: 256 rows, 64 cols exact)
    int aOff[4], aDst[4];
    #pragma unroll
    for (int q = 0; q < 4; q++) {
        int e = tid + q * 256, row = e >> 2, c = e & 3;
        aOff[q] = row * KDIM + c * 8;
        aDst[q] = row * APITCH + c * 16;
    }
    const int bRow = tid >> 3;                 // 0..31
    const int bCc  = tid & 7;                  // 0..7
    const size_t bOff = (size_t)bRow * HW + nBase + bCc * 8;
    const uint32_t bDst = bRow * BPITCH + bCc * 16;

    float acc[4][4][4];
    #pragma unroll
    for (int i = 0; i < 4; i++)
        #pragma unroll
        for (int j = 0; j < 4; j++)
            #pragma unroll
            for (int q = 0; q < 4; q++) acc[i][j][q] = 0.f;

    #define ISSUE1(ST, KO)                                                       \
        do {                                                                     \
            _Pragma("unroll")                                                    \
            for (int q = 0; q < 4; q++) {                                        \
                cpa16((ST) + AHI_OFF + aDst[q], Ahi_g + aOff[q] + (KO), true);   \
                cpa16((ST) + ALO_OFF + aDst[q], Alo_g + aOff[q] + (KO), true);   \
            }                                                                    \
            cpa16((ST) + BHI_OFF + bDst, Bhi_g + bofs + bOff + (size_t)(KO) * HW, true); \
            cpa16((ST) + BLO_OFF + bDst, Blo_g + bofs + bOff + (size_t)(KO) * HW, true); \
        } while (0)

    ISSUE1(sb, 0);
    cpa_commit();
    ISSUE1(sb + STAGE, 32);
    cpa_commit();

    const int lane15 = lane & 15;
    const int laneHi = lane >> 4;
    const int kB     = (lane >> 3) & 1;
    const int lane7  = lane & 7;
    const uint32_t aFragBase = (wm * 64 + lane15) * APITCH + laneHi * 16;
    const uint32_t bFragRow  = kB * 8 + lane7;
    const uint32_t bFragCol  = (wn * 32 + laneHi * 8) * 2;

    #pragma unroll 1
    for (int c = 0; c < 8; c++) {
        cpa_wait1();
        __syncthreads();
        const uint32_t st = sb + (c & 1) * STAGE;

        #pragma unroll
        for (int ks = 0; ks < 2; ks++) {
            uint32_t ah[4][4], bh[4][2];
            #pragma unroll
            for (int i = 0; i < 4; i++)
                ldmx4(ah[i], st + AHI_OFF + aFragBase + i * 16 * APITCH + ks * 32);
            {
                uint32_t r[4];
                ldmx4t(r, st + BHI_OFF + (ks * 16 + bFragRow) * BPITCH + bFragCol);
                bh[0][0] = r[0]; bh[0][1] = r[1]; bh[1][0] = r[2]; bh[1][1] = r[3];
                ldmx4t(r, st + BHI_OFF + (ks * 16 + bFragRow) * BPITCH + bFragCol + 32);
                bh[2][0] = r[0]; bh[2][1] = r[1]; bh[3][0] = r[2]; bh[3][1] = r[3];
            }
            #pragma unroll
            for (int i = 0; i < 4; i++)
                #pragma unroll
                for (int j = 0; j < 4; j++)
                    mma16816(acc[i][j], ah[i], bh[j][0], bh[j][1]);
            {
                uint32_t bl[4][2], r[4];
                ldmx4t(r, st + BLO_OFF + (ks * 16 + bFragRow) * BPITCH + bFragCol);
                bl[0][0] = r[0]; bl[0][1] = r[1]; bl[1][0] = r[2]; bl[1][1] = r[3];
                ldmx4t(r, st + BLO_OFF + (ks * 16 + bFragRow) * BPITCH + bFragCol + 32);
                bl[2][0] = r[0]; bl[2][1] = r[1]; bl[3][0] = r[2]; bl[3][1] = r[3];
                #pragma unroll
                for (int i = 0; i < 4; i++)
                    #pragma unroll
                    for (int j = 0; j < 4; j++)
                        mma16816(acc[i][j], ah[i], bl[j][0], bl[j][1]);
            }
            {
                uint32_t al[4];
                #pragma unroll
                for (int i = 0; i < 4; i++) {
                    ldmx4(al, st + ALO_OFF + aFragBase + i * 16 * APITCH + ks * 32);
                    #pragma unroll
                    for (int j = 0; j < 4; j++)
                        mma16816(acc[i][j], al, bh[j][0], bh[j][1]);
                }
            }
        }
        __syncthreads();
        if (c + 2 < 8) ISSUE1(sb + (c & 1) * STAGE, (c + 2) * 32);
        cpa_commit();
    }
    #undef ISSUE1

    // ---- drain phase-1 copies, then repurpose SMEM ----
    cpa_wait0();
    __syncthreads();

    // phase-2 W2 loader coordinates (80 rows padded, valid < 65)
    // q0: rows 0..63 (all threads); q1: rows 64..79 (tid < 64), valid only row 64
    const int w2r0 = tid >> 2, w2c0 = tid & 3;
    const int w2r1 = 64 + (tid >> 2), w2c1 = tid & 3;
    const bool w2a1 = tid < 64;
    const bool w2ok1 = w2a1 && (w2r1 < OUTCH);
    const int w2Off0 = w2r0 * KDIM + w2c0 * 8;
    const int w2Off1 = w2ok1 ? (w2r1 * KDIM + w2c1 * 8) : 0;
    const uint32_t w2Dst0 = w2r0 * 80 + w2c0 * 16;
    const uint32_t w2Dst1 = w2r1 * 80 + w2c1 * 16;

    #define ISSUE2(ST, KO)                                                       \
        do {                                                                     \
            cpa16((ST) + w2Dst0,        W2hi_g + w2Off0 + (KO), true);           \
            cpa16((ST) + 6400 + w2Dst0, W2lo_g + w2Off0 + (KO), true);           \
            if (w2a1) {                                                          \
                cpa16((ST) + w2Dst1,        W2hi_g + w2Off1 + (KO), w2ok1);      \
                cpa16((ST) + 6400 + w2Dst1, W2lo_g + w2Off1 + (KO), w2ok1);      \
            }                                                                    \
        } while (0)

    // issue W2 chunks 0,1 now so they fly while we write hidden to SMEM
    ISSUE2(sb + W2BASE, 0);
    cpa_commit();
    ISSUE2(sb + W2BASE + W2STG, 32);
    cpa_commit();

    // ---- write hidden (bias + leaky + split) into SMEM B-layout ----
    const int g   = lane >> 2;
    const int tig = lane & 3;
    #pragma unroll
    for (int i = 0; i < 4; i++) {
        const int m0 = wm * 64 + i * 16 + g;
        const float bv0 = bias1[m0];
        const float bv1 = bias1[m0 + 8];
        #pragma unroll
        for (int j = 0; j < 4; j++) {
            const int p = wn * 32 + j * 8 + tig * 2;
            float f0 = acc[i][j][0] + bv0; f0 = f0 >= 0.f ? f0 : 0.01f * f0;
            float f1 = acc[i][j][1] + bv0; f1 = f1 >= 0.f ? f1 : 0.01f * f1;
            float f2 = acc[i][j][2] + bv1; f2 = f2 >= 0.f ? f2 : 0.01f * f2;
            float f3 = acc[i][j][3] + bv1; f3 = f3 >= 0.f ? f3 : 0.01f * f3;
            __nv_bfloat16 h0, h1, h2, h3, l0, l1, l2, l3;
            split1(f0, h0, l0); split1(f1, h1, l1);
            split1(f2, h2, l2); split1(f3, h3, l3);
            *(uint32_t*)(smem + HIDHI + m0 * BPITCH + p * 2)       = pk2(h0, h1);
            *(uint32_t*)(smem + HIDLO + m0 * BPITCH + p * 2)       = pk2(l0, l1);
            *(uint32_t*)(smem + HIDHI + (m0 + 8) * BPITCH + p * 2) = pk2(h2, h3);
            *(uint32_t*)(smem + HIDLO + (m0 + 8) * BPITCH + p * 2) = pk2(l2, l3);
        }
    }
    __syncthreads();

    // ---- phase 2: out2[65][64] = W2 @ hidden + b2 ----
    // 8 warps: warp w owns n-frag w (8 cols), 5 m-frags (80 rows padded)
    float acc2[5][4];
    #pragma unroll
    for (int i = 0; i < 5; i++)
        #pragma unroll
        for (int q = 0; q < 4; q++) acc2[i][q] = 0.f;

    const uint32_t a2Frag = lane15 * 80 + laneHi * 16;
    const uint32_t b2Col  = wid * 16;

    #pragma unroll 1
    for (int c = 0; c < 8; c++) {
        cpa_wait1();
        __syncthreads();
        const uint32_t st = sb + W2BASE + (c & 1) * W2STG;

        #pragma unroll
        for (int ks = 0; ks < 2; ks++) {
            uint32_t bh0, bh1, bl0, bl1;
            const uint32_t hidRow = (c * 32 + ks * 16 + lane15) * BPITCH + b2Col;
            ldmx2t(bh0, bh1, sb + HIDHI + hidRow);
            ldmx2t(bl0, bl1, sb + HIDLO + hidRow);
            #pragma unroll
            for (int i = 0; i < 5; i++) {
                uint32_t ah[4], al[4];
                ldmx4(ah, st + a2Frag + i * 16 * 80 + ks * 32);
                mma16816(acc2[i], ah, bh0, bh1);
                mma16816(acc2[i], ah, bl0, bl1);
                ldmx4(al, st + 6400 + a2Frag + i * 16 * 80 + ks * 32);
                mma16816(acc2[i], al, bh0, bh1);
            }
        }
        __syncthreads();
        if (c + 2 < 8) ISSUE2(sb + W2BASE + (c & 1) * W2STG, (c + 2) * 32);
        cpa_commit();
    }
    #undef ISSUE2

    // ---- phase-2 epilogue: store out2 ----
    const int p = nBase + wid * 8 + tig * 2;
    #pragma unroll
    for (int i = 0; i < 5; i++) {
        const int m0 = i * 16 + g;
        const int m1 = m0 + 8;
        if (m0 < OUTCH) {
            const float bv = bias2[m0];
            float2 v = make_float2(acc2[i][0] + bv, acc2[i][1] + bv);
            *(float2*)&g_out2[((size_t)b * OUTCH + m0) * HW + p] = v;
        }
        if (m1 < OUTCH) {
            const float bv = bias2[m1];
            float2 v = make_float2(acc2[i][2] + bv, acc2[i][3] + bv);
            *(float2*)&g_out2[((size_t)b * OUTCH + m1) * HW + p] = v;
        }
    }
}

// ---------------------------------------------------------------------------
__global__ __launch_bounds__(256)
void head_kernel(const float* __restrict__ anc,
                 const float* __restrict__ bboxes,
                 float* __restrict__ iou_out)
{
    __shared__ float bx1[NBOX], by1[NBOX], bx2[NBOX], by2[NBOX], ga[NBOX];
    const int b = blockIdx.z;
    const int a = blockIdx.y;
    const int tid  = threadIdx.x;
    const int wid  = tid >> 5;
    const int lane = tid & 31;

    if (tid < NBOX) {
        const float* bb = bboxes + ((size_t)b * NBOX + tid) * 5;
        float x1 = bb[0], y1 = bb[1], x2 = bb[2], y2 = bb[3];
        bx1[tid] = x1; by1[tid] = y1; bx2[tid] = x2; by2[tid] = y2;
        ga[tid] = (x2 - x1) * (y2 - y1);
    }
    __syncthreads();

    const float wa = anc[a * 2 + 0], ha = anc[a * 2 + 1];
    const float* o = g_out2 + (size_t)b * OUTCH * HW;
    const int pBase = blockIdx.x * 128 + wid * 16;

    for (int q = 0; q < 16; q++) {
        int p = pBase + q;
        if (p >= HW) break;
        float tx = o[(5 * a + 1) * HW + p];
        float ty = o[(5 * a + 2) * HW + p];
        float tw = o[(5 * a + 3) * HW + p];
        float th = o[(5 * a + 4) * HW + p];
        int h = p / WW, w = p % WW;
        float cx = (w + 0.5f) + tx;
        float cy = (h + 0.5f) + ty;
        float nw = wa * expf(tw);
        float nh = ha * expf(th);
        float px1 = cx - nw * 0.5f, px2 = cx + nw * 0.5f;
        float py1 = cy - nh * 0.5f, py2 = cy + nh * 0.5f;
        float parea = (px2 - px1) * (py2 - py1);

        float* orow = iou_out + (((size_t)b * A_NUM + a) * HW + p) * NBOX;
        #pragma unroll
        for (int gg = 0; gg < 2; gg++) {
            int gi = lane + gg * 32;
            float ix1 = fmaxf(px1, bx1[gi]);
            float iy1 = fmaxf(py1, by1[gi]);
            float ix2 = fminf(px2, bx2[gi]);
            float iy2 = fminf(py2, by2[gi]);
            float inter = fmaxf(ix2 - ix1, 0.f) * fmaxf(iy2 - iy1, 0.f);
            orow[gi] = inter / (ga[gi] + parea - inter);
        }
    }
}

// ---------------------------------------------------------------------------
__global__ __launch_bounds__(64)
void loss_part(const int* __restrict__ pos_idx,
               const int* __restrict__ neg_idx,
               const float* __restrict__ gt_off)
{
    __shared__ float red[64];
    const int tid = threadIdx.x;
    const int m   = blockIdx.x * 64 + tid;
    float s = 0.f;
    {
        int idx = pos_idx[m];
        int b   = idx / (A_NUM * HW);
        int rem = idx % (A_NUM * HW);
        int a   = rem / HW;
        int p   = rem % HW;
        const float* o = g_out2 + ((size_t)b * OUTCH + 5 * a) * HW + p;
        float c  = o[0];
        float sc = 1.f / (1.f + expf(-c));
        float d  = sc - 1.f;
        s += 0.5f * d * d;
        #pragma unroll
        for (int k = 0; k < 4; k++) {
            float dd = o[(size_t)(1 + k) * HW] - gt_off[m * 4 + k];
            s += dd * dd;
        }
        int nidx = neg_idx[m];
        int nb   = nidx / (A_NUM * HW);
        int nrem = nidx % (A_NUM * HW);
        int na   = nrem / HW;
        int np   = nrem % HW;
        float nc = g_out2[((size_t)nb * OUTCH + 5 * na) * HW + np];
        float nsc = 1.f / (1.f + expf(-nc));
        s += 0.5f * nsc * nsc;
    }
    red[tid] = s;
    __syncthreads();
    for (int st = 32; st > 0; st >>= 1) {
        if (tid < st) red[tid] += red[tid + st];
        __syncthreads();
    }
    if (tid == 0) g_loss_part[blockIdx.x] = red[0];
}

__global__ void loss_final(float* __restrict__ out0)
{
    float s = 0.f;
    #pragma unroll
    for (int i = 0; i < 32; i++) s += g_loss_part[i];
    out0[0] = s / (float)MPOS;
}

// ---------------------------------------------------------------------------
__global__ __launch_bounds__(256)
void class_kernel(const int* __restrict__ pos_idx,
                  float* __restrict__ out_cls)
{
    int t = blockIdx.x * blockDim.x + threadIdx.x;
    if (t >= MPOS * C_NUM) return;
    int m = t / C_NUM;
    int c = t % C_NUM;
    int idx = pos_idx[m];
    int b = idx / (A_NUM * HW);
    int p = idx % HW;
    out_cls[t] = g_out2[((size_t)b * OUTCH + 5 * A_NUM + c) * HW + p];
}

// ---------------------------------------------------------------------------
extern "C" void kernel_launch(void* const* d_in, const int* in_sizes, int n_in,
                              void* d_out, int out_size)
{
    const float* features = (const float*)d_in[0];
    const float* w1       = (const float*)d_in[1];
    const float* b1       = (const float*)d_in[2];
    const float* w2       = (const float*)d_in[3];
    const float* b2       = (const float*)d_in[4];
    const float* anc      = (const float*)d_in[5];
    const float* bboxes   = (const float*)d_in[7];
    const float* gt_off   = (const float*)d_in[8];
    const int*   pos_idx  = (const int*)d_in[9];
    const int*   neg_idx  = (const int*)d_in[10];

    float* out      = (float*)d_out;
    float* loss_out = out;
    float* iou_out  = out + 1;
    float* cls_out  = out + 1 + (size_t)BATCH * A_NUM * HW * NBOX;

    cudaFuncSetAttribute(gemm_fused,
                         cudaFuncAttributeMaxDynamicSharedMemorySize, GEMM_SMEM);

    __nv_bfloat16 *w1h, *w1l, *w2h, *w2l, *fh, *fl;
    cudaGetSymbolAddress((void**)&w1h, g_w1_hi);
    cudaGetSymbolAddress((void**)&w1l, g_w1_lo);
    cudaGetSymbolAddress((void**)&w2h, g_w2_hi);
    cudaGetSymbolAddress((void**)&w2l, g_w2_lo);
    cudaGetSymbolAddress((void**)&fh,  g_feat_hi);
    cudaGetSymbolAddress((void**)&fl,  g_feat_lo);

    convert_split<<<(KDIM * KDIM / 4 + 255) / 256, 256>>>(w1, w1h, w1l, KDIM * KDIM / 4);
    convert_split<<<(OUTCH * KDIM / 4 + 255) / 256, 256>>>(w2, w2h, w2l, OUTCH * KDIM / 4);
    {
        int n4 = (int)((size_t)BATCH * KDIM * HW / 4);
        convert_split<<<(n4 + 255) / 256, 256>>>(features, fh, fl, n4);
    }

    gemm_fused<<<dim3(49, 1, BATCH), 256, GEMM_SMEM>>>(w1h, w1l, fh, fl, b1,
                                                       w2h, w2l, b2);

    head_kernel<<<dim3(25, A_NUM, BATCH), 256>>>(anc, bboxes, iou_out);
    loss_part<<<32, 64>>>(pos_idx, neg_idx, gt_off);
    loss_final<<<1, 1>>>(loss_out);
    class_kernel<<<(MPOS * C_NUM + 255) / 256, 256>>>(pos_idx, cls_out);
}

// round 13
// speedup vs baseline: 1.2593x; 1.1296x over previous
#include <cuda_runtime.h>
#include <cuda_bf16.h>
#include <math.h>
#include <stdint.h>

#define A_NUM   9
#define C_NUM   20
#define OUTCH   65
#define BATCH   32
#define KDIM    256
#define HH      56
#define WW      56
#define HW      3136
#define NBOX    64
#define MPOS    2048

// ---- global scratch ----
__device__ __nv_bfloat16 g_w1_hi[KDIM * KDIM];
__device__ __nv_bfloat16 g_w1_lo[KDIM * KDIM];
__device__ __nv_bfloat16 g_w2_hi[OUTCH * KDIM];
__device__ __nv_bfloat16 g_w2_lo[OUTCH * KDIM];
__device__ float         g_out2 [(size_t)BATCH * OUTCH * HW];   // [b][m][p]
__device__ float         g_loss_part[32];

// ---- helpers ----
__device__ __forceinline__ uint32_t smem_u32(const void* p) {
    uint32_t a;
    asm("{ .reg .u64 t; cvta.to.shared.u64 t, %1; cvt.u32.u64 %0, t; }"
        : "=r"(a) : "l"(p));
    return a;
}
__device__ __forceinline__ uint32_t pk2(__nv_bfloat16 a, __nv_bfloat16 b) {
    __nv_bfloat162 t; t.x = a; t.y = b;
    return *(uint32_t*)&t;
}
__device__ __forceinline__ void split1(float x, __nv_bfloat16& h, __nv_bfloat16& l) {
    h = __float2bfloat16(x);
    l = __float2bfloat16(x - __bfloat162float(h));
}
__device__ __forceinline__ void mma16816(float* c,
    const uint32_t* a, uint32_t b0, uint32_t b1)
{
    asm volatile(
        "mma.sync.aligned.m16n8k16.row.col.f32.bf16.bf16.f32 "
        "{%0,%1,%2,%3}, {%4,%5,%6,%7}, {%8,%9}, {%0,%1,%2,%3};"
        : "+f"(c[0]), "+f"(c[1]), "+f"(c[2]), "+f"(c[3])
        : "r"(a[0]), "r"(a[1]), "r"(a[2]), "r"(a[3]), "r"(b0), "r"(b1));
}
__device__ __forceinline__ void ldmx4(uint32_t* r, uint32_t addr) {
    asm volatile("ldmatrix.sync.aligned.m8n8.x4.shared.b16 {%0,%1,%2,%3}, [%4];"
        : "=r"(r[0]), "=r"(r[1]), "=r"(r[2]), "=r"(r[3]) : "r"(addr));
}
__device__ __forceinline__ void ldmx4t(uint32_t* r, uint32_t addr) {
    asm volatile("ldmatrix.sync.aligned.m8n8.x4.trans.shared.b16 {%0,%1,%2,%3}, [%4];"
        : "=r"(r[0]), "=r"(r[1]), "=r"(r[2]), "=r"(r[3]) : "r"(addr));
}
__device__ __forceinline__ void cpa16(uint32_t dst, const void* src, bool ok) {
    uint32_t sz = ok ? 16u : 0u;
    asm volatile("cp.async.cg.shared.global [%0], [%1], 16, %2;"
                 :: "r"(dst), "l"(src), "r"(sz));
}
__device__ __forceinline__ void cpa_commit() {
    asm volatile("cp.async.commit_group;" ::: "memory");
}
__device__ __forceinline__ void cpa_wait1() {
    asm volatile("cp.async.wait_group 1;" ::: "memory");
}
__device__ __forceinline__ void cpa_wait0() {
    asm volatile("cp.async.wait_group 0;" ::: "memory");
}

// ---- SMEM layout ----
// Phase 1: per-stage (stride 49152): A-hi [256m][k32] pitch 80 at +0,
//          A-lo at +20480, B fp32 staging [k32][64p] pitch 256 at +40960.
// Fixed:   converted B-hi [k32][64p] pitch 144 at 98304, B-lo at 102912.
#define APITCH    80
#define BPITCH    144
#define ST_STRIDE 49152
#define AHI_OFF   0
#define ALO_OFF   20480
#define BF32_OFF  40960
#define BHI_OFF   98304
#define BLO_OFF   102912
// Phase 2 (reuses region): hidden [k256][64p] pitch 144: hi 0, lo 36864;
// W2 chunk buffers [80m][k32] pitch 80 at 73728 + st*12800 (hi +0, lo +6400)
#define HIDHI     0
#define HIDLO     36864
#define W2BASE    73728
#define W2STG     12800
#define GEMM_SMEM 107520     // 2 CTAs/SM (210KB of 228KB)

// ---------------------------------------------------------------------------
__global__ __launch_bounds__(256)
void convert_split(const float* __restrict__ src,
                   __nv_bfloat16* __restrict__ hi,
                   __nv_bfloat16* __restrict__ lo, int n4)
{
    int t = blockIdx.x * blockDim.x + threadIdx.x;
    if (t >= n4) return;
    float4 v = ((const float4*)src)[t];
    __nv_bfloat16 h0, h1, h2, h3, l0, l1, l2, l3;
    split1(v.x, h0, l0); split1(v.y, h1, l1);
    split1(v.z, h2, l2); split1(v.w, h3, l3);
    ((uint2*)hi)[t] = make_uint2(pk2(h0, h1), pk2(h2, h3));
    ((uint2*)lo)[t] = make_uint2(pk2(l0, l1), pk2(l2, l3));
}

// ---------------------------------------------------------------------------
// Fused conv1+conv2, raw fp32 features converted in-kernel.
// Block: 256m x 64p (grid 49 x 32, exact). Per chunk:
//   wait1 -> sync -> convert(c) -> sync -> MMA(c) -> sync -> issue(c+2) -> commit
// (cp.async groups are per-thread; each hazard sits behind a barrier.)
// ---------------------------------------------------------------------------
__global__ __launch_bounds__(256, 2)
void gemm_fused(const __nv_bfloat16* __restrict__ Ahi_g,
                const __nv_bfloat16* __restrict__ Alo_g,
                const float* __restrict__ Fraw,
                const float* __restrict__ bias1,
                const __nv_bfloat16* __restrict__ W2hi_g,
                const __nv_bfloat16* __restrict__ W2lo_g,
                const float* __restrict__ bias2)
{
    extern __shared__ char smem[];
    const uint32_t sb = smem_u32(smem);

    const int b     = blockIdx.z;
    const int nBase = blockIdx.x * 64;         // 49*64 = 3136 exact
    const int tid   = threadIdx.x;
    const int wid   = tid >> 5;
    const int lane  = tid & 31;
    const int wm    = wid >> 1;                // 0..3 (m offset wm*64)
    const int wn    = wid & 1;                 // 0..1 (p offset wn*32)

    const float* fB = Fraw + (size_t)b * KDIM * HW;

    // phase-1 A loader (W1 256x256, no guards)
    int aOff[4], aDst[4];
    #pragma unroll
    for (int q = 0; q < 4; q++) {
        int e = tid + q * 256, row = e >> 2, c = e & 3;
        aOff[q] = row * KDIM + c * 8;
        aDst[q] = row * APITCH + c * 16;
    }
    // phase-1 B fp32 loader: 2x float4 per thread
    int fRow[2], fDst[2];
    size_t fOff[2];
    #pragma unroll
    for (int q = 0; q < 2; q++) {
        int e = tid + q * 256, row = e >> 4, c4 = e & 15;
        fRow[q] = row;
        fOff[q] = (size_t)row * HW + nBase + c4 * 4;
        fDst[q] = row * 256 + c4 * 16;
    }

    float acc[4][4][4];
    #pragma unroll
    for (int i = 0; i < 4; i++)
        #pragma unroll
        for (int j = 0; j < 4; j++)
            #pragma unroll
            for (int q = 0; q < 4; q++) acc[i][j][q] = 0.f;

    #define ISSUE1(ST, KO)                                                       \
        do {                                                                     \
            _Pragma("unroll")                                                    \
            for (int q = 0; q < 4; q++) {                                        \
                cpa16((ST) + AHI_OFF + aDst[q], Ahi_g + aOff[q] + (KO), true);   \
                cpa16((ST) + ALO_OFF + aDst[q], Alo_g + aOff[q] + (KO), true);   \
            }                                                                    \
            _Pragma("unroll")                                                    \
            for (int q = 0; q < 2; q++)                                          \
                cpa16((ST) + BF32_OFF + fDst[q],                                 \
                      fB + fOff[q] + (size_t)(KO) * HW, true);                   \
        } while (0)

    ISSUE1(sb, 0);
    cpa_commit();
    ISSUE1(sb + ST_STRIDE, 32);
    cpa_commit();

    const int lane15 = lane & 15;
    const int laneHi = lane >> 4;
    const int kB     = (lane >> 3) & 1;
    const int lane7  = lane & 7;
    const uint32_t aFragBase = (wm * 64 + lane15) * APITCH + laneHi * 16;
    const uint32_t bFragRow  = kB * 8 + lane7;
    const uint32_t bFragCol  = (wn * 32 + laneHi * 8) * 2;

    #pragma unroll 1
    for (int c = 0; c < 8; c++) {
        cpa_wait1();
        __syncthreads();          // chunk c (A + fp32 B) published; BHI readers done
        const uint32_t st = sb + (c & 1) * ST_STRIDE;

        // convert fp32 B -> split bf16 into fixed BHI/BLO
        #pragma unroll
        for (int q = 0; q < 2; q++) {
            int e = tid + q * 256, row = e >> 4, c4 = e & 15;
            float4 v = *(const float4*)(smem + (c & 1) * ST_STRIDE + BF32_OFF
                                        + row * 256 + c4 * 16);
            __nv_bfloat16 h0, h1, h2, h3, l0, l1, l2, l3;
            split1(v.x, h0, l0); split1(v.y, h1, l1);
            split1(v.z, h2, l2); split1(v.w, h3, l3);
            *(uint2*)(smem + BHI_OFF + row * BPITCH + c4 * 8) =
                make_uint2(pk2(h0, h1), pk2(h2, h3));
            *(uint2*)(smem + BLO_OFF + row * BPITCH + c4 * 8) =
                make_uint2(pk2(l0, l1), pk2(l2, l3));
        }
        __syncthreads();          // converted B visible to all warps

        #pragma unroll
        for (int ks = 0; ks < 2; ks++) {
            uint32_t ah[4][4], bh[4][2];
            #pragma unroll
            for (int i = 0; i < 4; i++)
                ldmx4(ah[i], st + AHI_OFF + aFragBase + i * 16 * APITCH + ks * 32);
            {
                uint32_t r[4];
                ldmx4t(r, sb + BHI_OFF + (ks * 16 + bFragRow) * BPITCH + bFragCol);
                bh[0][0] = r[0]; bh[0][1] = r[1]; bh[1][0] = r[2]; bh[1][1] = r[3];
                ldmx4t(r, sb + BHI_OFF + (ks * 16 + bFragRow) * BPITCH + bFragCol + 32);
                bh[2][0] = r[0]; bh[2][1] = r[1]; bh[3][0] = r[2]; bh[3][1] = r[3];
            }
            #pragma unroll
            for (int i = 0; i < 4; i++)
                #pragma unroll
                for (int j = 0; j < 4; j++)
                    mma16816(acc[i][j], ah[i], bh[j][0], bh[j][1]);
            {
                uint32_t bl[4][2], r[4];
                ldmx4t(r, sb + BLO_OFF + (ks * 16 + bFragRow) * BPITCH + bFragCol);
                bl[0][0] = r[0]; bl[0][1] = r[1]; bl[1][0] = r[2]; bl[1][1] = r[3];
                ldmx4t(r, sb + BLO_OFF + (ks * 16 + bFragRow) * BPITCH + bFragCol + 32);
                bl[2][0] = r[0]; bl[2][1] = r[1]; bl[3][0] = r[2]; bl[3][1] = r[3];
                #pragma unroll
                for (int i = 0; i < 4; i++)
                    #pragma unroll
                    for (int j = 0; j < 4; j++)
                        mma16816(acc[i][j], ah[i], bl[j][0], bl[j][1]);
            }
            {
                uint32_t al[4];
                #pragma unroll
                for (int i = 0; i < 4; i++) {
                    ldmx4(al, st + ALO_OFF + aFragBase + i * 16 * APITCH + ks * 32);
                    #pragma unroll
                    for (int j = 0; j < 4; j++)
                        mma16816(acc[i][j], al, bh[j][0], bh[j][1]);
                }
            }
        }
        __syncthreads();          // MMA(c) reads done before stage refill
        if (c + 2 < 8) ISSUE1(sb + (c & 1) * ST_STRIDE, (c + 2) * 32);
        cpa_commit();
    }
    #undef ISSUE1

    cpa_wait0();
    __syncthreads();

    // phase-2 W2 loader
    const int w2r0 = tid >> 2, w2c0 = tid & 3;
    const int w2r1 = 64 + (tid >> 2), w2c1 = tid & 3;
    const bool w2a1 = tid < 64;
    const bool w2ok1 = w2a1 && (w2r1 < OUTCH);
    const int w2Off0 = w2r0 * KDIM + w2c0 * 8;
    const int w2Off1 = w2ok1 ? (w2r1 * KDIM + w2c1 * 8) : 0;
    const uint32_t w2Dst0 = w2r0 * 80 + w2c0 * 16;
    const uint32_t w2Dst1 = w2r1 * 80 + w2c1 * 16;

    #define ISSUE2(ST, KO)                                                       \
        do {                                                                     \
            cpa16((ST) + w2Dst0,        W2hi_g + w2Off0 + (KO), true);           \
            cpa16((ST) + 6400 + w2Dst0, W2lo_g + w2Off0 + (KO), true);           \
            if (w2a1) {                                                          \
                cpa16((ST) + w2Dst1,        W2hi_g + w2Off1 + (KO), w2ok1);      \
                cpa16((ST) + 6400 + w2Dst1, W2lo_g + w2Off1 + (KO), w2ok1);      \
            }                                                                    \
        } while (0)

    ISSUE2(sb + W2BASE, 0);
    cpa_commit();
    ISSUE2(sb + W2BASE + W2STG, 32);
    cpa_commit();

    // write hidden (bias + leaky + split) into SMEM B-layout
    const int g   = lane >> 2;
    const int tig = lane & 3;
    #pragma unroll
    for (int i = 0; i < 4; i++) {
        const int m0 = wm * 64 + i * 16 + g;
        const float bv0 = bias1[m0];
        const float bv1 = bias1[m0 + 8];
        #pragma unroll
        for (int j = 0; j < 4; j++) {
            const int p = wn * 32 + j * 8 + tig * 2;
            float f0 = acc[i][j][0] + bv0; f0 = f0 >= 0.f ? f0 : 0.01f * f0;
            float f1 = acc[i][j][1] + bv0; f1 = f1 >= 0.f ? f1 : 0.01f * f1;
            float f2 = acc[i][j][2] + bv1; f2 = f2 >= 0.f ? f2 : 0.01f * f2;
            float f3 = acc[i][j][3] + bv1; f3 = f3 >= 0.f ? f3 : 0.01f * f3;
            __nv_bfloat16 h0, h1, h2, h3, l0, l1, l2, l3;
            split1(f0, h0, l0); split1(f1, h1, l1);
            split1(f2, h2, l2); split1(f3, h3, l3);
            *(uint32_t*)(smem + HIDHI + m0 * BPITCH + p * 2)       = pk2(h0, h1);
            *(uint32_t*)(smem + HIDLO + m0 * BPITCH + p * 2)       = pk2(l0, l1);
            *(uint32_t*)(smem + HIDHI + (m0 + 8) * BPITCH + p * 2) = pk2(h2, h3);
            *(uint32_t*)(smem + HIDLO + (m0 + 8) * BPITCH + p * 2) = pk2(l2, l3);
        }
    }
    __syncthreads();

    // ---- phase 2: out2[65][64] = W2 @ hidden + b2 ----
    // warps (mw 0..3, nw 0..1); mw owns m-frags {0,1},{2},{3},{4}; nw owns 32 cols
    const int mw = wid >> 1;
    const int nw = wid & 1;
    const int ibase = (mw == 0) ? 0 : (mw + 1);   // 0,2,3,4
    const int icnt  = (mw == 0) ? 2 : 1;

    float acc2[2][4][4];
    #pragma unroll
    for (int ii = 0; ii < 2; ii++)
        #pragma unroll
        for (int j = 0; j < 4; j++)
            #pragma unroll
            for (int q = 0; q < 4; q++) acc2[ii][j][q] = 0.f;

    const uint32_t a2Frag = lane15 * 80 + laneHi * 16;
    const uint32_t b2Col  = (nw * 32 + laneHi * 8) * 2;

    #pragma unroll 1
    for (int c = 0; c < 8; c++) {
        cpa_wait1();
        __syncthreads();
        const uint32_t st = sb + W2BASE + (c & 1) * W2STG;

        #pragma unroll
        for (int ks = 0; ks < 2; ks++) {
            const uint32_t hidRow = (c * 32 + ks * 16 + bFragRow) * BPITCH + b2Col;
            uint32_t bh[4][2], bl[4][2], r[4];
            ldmx4t(r, sb + HIDHI + hidRow);
            bh[0][0] = r[0]; bh[0][1] = r[1]; bh[1][0] = r[2]; bh[1][1] = r[3];
            ldmx4t(r, sb + HIDHI + hidRow + 32);
            bh[2][0] = r[0]; bh[2][1] = r[1]; bh[3][0] = r[2]; bh[3][1] = r[3];
            ldmx4t(r, sb + HIDLO + hidRow);
            bl[0][0] = r[0]; bl[0][1] = r[1]; bl[1][0] = r[2]; bl[1][1] = r[3];
            ldmx4t(r, sb + HIDLO + hidRow + 32);
            bl[2][0] = r[0]; bl[2][1] = r[1]; bl[3][0] = r[2]; bl[3][1] = r[3];

            #pragma unroll
            for (int ii = 0; ii < 2; ii++) {
                if (ii < icnt) {
                    const int i = ibase + ii;
                    uint32_t ah[4], al[4];
                    ldmx4(ah, st + a2Frag + i * 16 * 80 + ks * 32);
                    ldmx4(al, st + 6400 + a2Frag + i * 16 * 80 + ks * 32);
                    #pragma unroll
                    for (int j = 0; j < 4; j++) {
                        mma16816(acc2[ii][j], ah, bh[j][0], bh[j][1]);
                        mma16816(acc2[ii][j], ah, bl[j][0], bl[j][1]);
                        mma16816(acc2[ii][j], al, bh[j][0], bh[j][1]);
                    }
                }
            }
        }
        __syncthreads();
        if (c + 2 < 8) ISSUE2(sb + W2BASE + (c & 1) * W2STG, (c + 2) * 32);
        cpa_commit();
    }
    #undef ISSUE2

    // phase-2 epilogue
    #pragma unroll
    for (int ii = 0; ii < 2; ii++) {
        if (ii < icnt) {
            const int i = ibase + ii;
            const int m0 = i * 16 + g;
            const int m1 = m0 + 8;
            #pragma unroll
            for (int j = 0; j < 4; j++) {
                const int p = nBase + nw * 32 + j * 8 + tig * 2;
                if (m0 < OUTCH) {
                    const float bv = bias2[m0];
                    float2 v = make_float2(acc2[ii][j][0] + bv, acc2[ii][j][1] + bv);
                    *(float2*)&g_out2[((size_t)b * OUTCH + m0) * HW + p] = v;
                }
                if (m1 < OUTCH) {
                    const float bv = bias2[m1];
                    float2 v = make_float2(acc2[ii][j][2] + bv, acc2[ii][j][3] + bv);
                    *(float2*)&g_out2[((size_t)b * OUTCH + m1) * HW + p] = v;
                }
            }
        }
    }
}

// ---------------------------------------------------------------------------
__global__ __launch_bounds__(256)
void head_kernel(const float* __restrict__ anc,
                 const float* __restrict__ bboxes,
                 float* __restrict__ iou_out)
{
    __shared__ float bx1[NBOX], by1[NBOX], bx2[NBOX], by2[NBOX], ga[NBOX];
    const int b = blockIdx.z;
    const int a = blockIdx.y;
    const int tid  = threadIdx.x;
    const int wid  = tid >> 5;
    const int lane = tid & 31;

    if (tid < NBOX) {
        const float* bb = bboxes + ((size_t)b * NBOX + tid) * 5;
        float x1 = bb[0], y1 = bb[1], x2 = bb[2], y2 = bb[3];
        bx1[tid] = x1; by1[tid] = y1; bx2[tid] = x2; by2[tid] = y2;
        ga[tid] = (x2 - x1) * (y2 - y1);
    }
    __syncthreads();

    const float wa = anc[a * 2 + 0], ha = anc[a * 2 + 1];
    const float* o = g_out2 + (size_t)b * OUTCH * HW;
    const int pBase = blockIdx.x * 128 + wid * 16;
    const int qmax = (HW - pBase) < 16 ? (HW - pBase) : 16;

    #pragma unroll 2
    for (int q = 0; q < qmax; q++) {
        int p = pBase + q;
        float tx = o[(5 * a + 1) * HW + p];
        float ty = o[(5 * a + 2) * HW + p];
        float tw = o[(5 * a + 3) * HW + p];
        float th = o[(5 * a + 4) * HW + p];
        int h = p / WW, w = p % WW;
        float cx = (w + 0.5f) + tx;
        float cy = (h + 0.5f) + ty;
        float nw = wa * __expf(tw);
        float nh = ha * __expf(th);
        float px1 = cx - nw * 0.5f, px2 = cx + nw * 0.5f;
        float py1 = cy - nh * 0.5f, py2 = cy + nh * 0.5f;
        float parea = (px2 - px1) * (py2 - py1);

        float* orow = iou_out + (((size_t)b * A_NUM + a) * HW + p) * NBOX;
        #pragma unroll
        for (int gg = 0; gg < 2; gg++) {
            int gi = lane + gg * 32;
            float ix1 = fmaxf(px1, bx1[gi]);
            float iy1 = fmaxf(py1, by1[gi]);
            float ix2 = fminf(px2, bx2[gi]);
            float iy2 = fminf(py2, by2[gi]);
            float inter = fmaxf(ix2 - ix1, 0.f) * fmaxf(iy2 - iy1, 0.f);
            orow[gi] = inter / (ga[gi] + parea - inter);
        }
    }
}

// ---------------------------------------------------------------------------
__global__ __launch_bounds__(64)
void loss_part(const int* __restrict__ pos_idx,
               const int* __restrict__ neg_idx,
               const float* __restrict__ gt_off)
{
    __shared__ float red[64];
    const int tid = threadIdx.x;
    const int m   = blockIdx.x * 64 + tid;
    float s = 0.f;
    {
        int idx = pos_idx[m];
        int b   = idx / (A_NUM * HW);
        int rem = idx % (A_NUM * HW);
        int a   = rem / HW;
        int p   = rem % HW;
        const float* o = g_out2 + ((size_t)b * OUTCH + 5 * a) * HW + p;
        float c  = o[0];
        float sc = 1.f / (1.f + expf(-c));
        float d  = sc - 1.f;
        s += 0.5f * d * d;
        #pragma unroll
        for (int k = 0; k < 4; k++) {
            float dd = o[(size_t)(1 + k) * HW] - gt_off[m * 4 + k];
            s += dd * dd;
        }
        int nidx = neg_idx[m];
        int nb   = nidx / (A_NUM * HW);
        int nrem = nidx % (A_NUM * HW);
        int na   = nrem / HW;
        int np   = nrem % HW;
        float nc = g_out2[((size_t)nb * OUTCH + 5 * na) * HW + np];
        float nsc = 1.f / (1.f + expf(-nc));
        s += 0.5f * nsc * nsc;
    }
    red[tid] = s;
    __syncthreads();
    for (int st = 32; st > 0; st >>= 1) {
        if (tid < st) red[tid] += red[tid + st];
        __syncthreads();
    }
    if (tid == 0) g_loss_part[blockIdx.x] = red[0];
}

__global__ void loss_final(float* __restrict__ out0)
{
    float s = 0.f;
    #pragma unroll
    for (int i = 0; i < 32; i++) s += g_loss_part[i];
    out0[0] = s / (float)MPOS;
}

// ---------------------------------------------------------------------------
__global__ __launch_bounds__(256)
void class_kernel(const int* __restrict__ pos_idx,
                  float* __restrict__ out_cls)
{
    int t = blockIdx.x * blockDim.x + threadIdx.x;
    if (t >= MPOS * C_NUM) return;
    int m = t / C_NUM;
    int c = t % C_NUM;
    int idx = pos_idx[m];
    int b = idx / (A_NUM * HW);
    int p = idx % HW;
    out_cls[t] = g_out2[((size_t)b * OUTCH + 5 * A_NUM + c) * HW + p];
}

// ---------------------------------------------------------------------------
extern "C" void kernel_launch(void* const* d_in, const int* in_sizes, int n_in,
                              void* d_out, int out_size)
{
    const float* features = (const float*)d_in[0];
    const float* w1       = (const float*)d_in[1];
    const float* b1       = (const float*)d_in[2];
    const float* w2       = (const float*)d_in[3];
    const float* b2       = (const float*)d_in[4];
    const float* anc      = (const float*)d_in[5];
    const float* bboxes   = (const float*)d_in[7];
    const float* gt_off   = (const float*)d_in[8];
    const int*   pos_idx  = (const int*)d_in[9];
    const int*   neg_idx  = (const int*)d_in[10];

    float* out      = (float*)d_out;
    float* loss_out = out;
    float* iou_out  = out + 1;
    float* cls_out  = out + 1 + (size_t)BATCH * A_NUM * HW * NBOX;

    cudaFuncSetAttribute(gemm_fused,
                         cudaFuncAttributeMaxDynamicSharedMemorySize, GEMM_SMEM);

    __nv_bfloat16 *w1h, *w1l, *w2h, *w2l;
    cudaGetSymbolAddress((void**)&w1h, g_w1_hi);
    cudaGetSymbolAddress((void**)&w1l, g_w1_lo);
    cudaGetSymbolAddress((void**)&w2h, g_w2_hi);
    cudaGetSymbolAddress((void**)&w2l, g_w2_lo);

    convert_split<<<(KDIM * KDIM / 4 + 255) / 256, 256>>>(w1, w1h, w1l, KDIM * KDIM / 4);
    convert_split<<<(OUTCH * KDIM / 4 + 255) / 256, 256>>>(w2, w2h, w2l, OUTCH * KDIM / 4);

    gemm_fused<<<dim3(49, 1, BATCH), 256, GEMM_SMEM>>>(w1h, w1l, features, b1,
                                                       w2h, w2l, b2);

    head_kernel<<<dim3(25, A_NUM, BATCH), 256>>>(anc, bboxes, iou_out);
    loss_part<<<32, 64>>>(pos_idx, neg_idx, gt_off);
    loss_final<<<1, 1>>>(loss_out);
    class_kernel<<<(MPOS * C_NUM + 255) / 256, 256>>>(pos_idx, cls_out);
}

// round 14
// speedup vs baseline: 1.5747x; 1.2505x over previous
#include <cuda_runtime.h>
#include <cuda_bf16.h>
#include <math.h>
#include <stdint.h>

#define A_NUM   9
#define C_NUM   20
#define OUTCH   65
#define BATCH   32
#define KDIM    256
#define HH      56
#define WW      56
#define HW      3136
#define NBOX    64
#define MPOS    2048

// ---- global scratch ----
__device__ __nv_bfloat16 g_w1_hi[KDIM * KDIM];
__device__ __nv_bfloat16 g_w1_lo[KDIM * KDIM];
__device__ __nv_bfloat16 g_w2_hi[OUTCH * KDIM];
__device__ __nv_bfloat16 g_w2_lo[OUTCH * KDIM];
__device__ float         g_out2 [(size_t)BATCH * OUTCH * HW];   // [b][m][p]
__device__ float         g_loss_part[32];

// ---- helpers ----
__device__ __forceinline__ uint32_t smem_u32(const void* p) {
    uint32_t a;
    asm("{ .reg .u64 t; cvta.to.shared.u64 t, %1; cvt.u32.u64 %0, t; }"
        : "=r"(a) : "l"(p));
    return a;
}
__device__ __forceinline__ uint32_t pk2(__nv_bfloat16 a, __nv_bfloat16 b) {
    __nv_bfloat162 t; t.x = a; t.y = b;
    return *(uint32_t*)&t;
}
__device__ __forceinline__ void split1(float x, __nv_bfloat16& h, __nv_bfloat16& l) {
    h = __float2bfloat16(x);
    l = __float2bfloat16(x - __bfloat162float(h));
}
__device__ __forceinline__ void mma16816(float* c,
    const uint32_t* a, uint32_t b0, uint32_t b1)
{
    asm volatile(
        "mma.sync.aligned.m16n8k16.row.col.f32.bf16.bf16.f32 "
        "{%0,%1,%2,%3}, {%4,%5,%6,%7}, {%8,%9}, {%0,%1,%2,%3};"
        : "+f"(c[0]), "+f"(c[1]), "+f"(c[2]), "+f"(c[3])
        : "r"(a[0]), "r"(a[1]), "r"(a[2]), "r"(a[3]), "r"(b0), "r"(b1));
}
__device__ __forceinline__ void ldmx4(uint32_t* r, uint32_t addr) {
    asm volatile("ldmatrix.sync.aligned.m8n8.x4.shared.b16 {%0,%1,%2,%3}, [%4];"
        : "=r"(r[0]), "=r"(r[1]), "=r"(r[2]), "=r"(r[3]) : "r"(addr));
}
__device__ __forceinline__ void ldmx4t(uint32_t* r, uint32_t addr) {
    asm volatile("ldmatrix.sync.aligned.m8n8.x4.trans.shared.b16 {%0,%1,%2,%3}, [%4];"
        : "=r"(r[0]), "=r"(r[1]), "=r"(r[2]), "=r"(r[3]) : "r"(addr));
}
__device__ __forceinline__ void cpa16(uint32_t dst, const void* src, bool ok) {
    uint32_t sz = ok ? 16u : 0u;
    asm volatile("cp.async.cg.shared.global [%0], [%1], 16, %2;"
                 :: "r"(dst), "l"(src), "r"(sz));
}
__device__ __forceinline__ void cpa_commit() {
    asm volatile("cp.async.commit_group;" ::: "memory");
}
__device__ __forceinline__ void cpa_wait1() {
    asm volatile("cp.async.wait_group 1;" ::: "memory");
}
__device__ __forceinline__ void cpa_wait0() {
    asm volatile("cp.async.wait_group 0;" ::: "memory");
}

// ---- SMEM layout ----
#define APITCH    80
#define BPITCH    144
#define ST_STRIDE 49152
#define AHI_OFF   0
#define ALO_OFF   20480
#define BF32_OFF  40960
#define BHI_OFF   98304
#define BLO_OFF   102912
#define HIDHI     0
#define HIDLO     36864
#define W2BASE    73728
#define W2STG     12800
#define GEMM_SMEM 107520     // 2 CTAs/SM (210KB of 228KB)

// ---------------------------------------------------------------------------
__global__ __launch_bounds__(256)
void convert_split(const float* __restrict__ src,
                   __nv_bfloat16* __restrict__ hi,
                   __nv_bfloat16* __restrict__ lo, int n4)
{
    int t = blockIdx.x * blockDim.x + threadIdx.x;
    if (t >= n4) return;
    float4 v = ((const float4*)src)[t];
    __nv_bfloat16 h0, h1, h2, h3, l0, l1, l2, l3;
    split1(v.x, h0, l0); split1(v.y, h1, l1);
    split1(v.z, h2, l2); split1(v.w, h3, l3);
    ((uint2*)hi)[t] = make_uint2(pk2(h0, h1), pk2(h2, h3));
    ((uint2*)lo)[t] = make_uint2(pk2(l0, l1), pk2(l2, l3));
}

// ---------------------------------------------------------------------------
// Fused conv1+conv2 (unchanged from R13-winning version).
// ---------------------------------------------------------------------------
__global__ __launch_bounds__(256, 2)
void gemm_fused(const __nv_bfloat16* __restrict__ Ahi_g,
                const __nv_bfloat16* __restrict__ Alo_g,
                const float* __restrict__ Fraw,
                const float* __restrict__ bias1,
                const __nv_bfloat16* __restrict__ W2hi_g,
                const __nv_bfloat16* __restrict__ W2lo_g,
                const float* __restrict__ bias2)
{
    extern __shared__ char smem[];
    const uint32_t sb = smem_u32(smem);

    const int b     = blockIdx.z;
    const int nBase = blockIdx.x * 64;
    const int tid   = threadIdx.x;
    const int wid   = tid >> 5;
    const int lane  = tid & 31;
    const int wm    = wid >> 1;
    const int wn    = wid & 1;

    const float* fB = Fraw + (size_t)b * KDIM * HW;

    int aOff[4], aDst[4];
    #pragma unroll
    for (int q = 0; q < 4; q++) {
        int e = tid + q * 256, row = e >> 2, c = e & 3;
        aOff[q] = row * KDIM + c * 8;
        aDst[q] = row * APITCH + c * 16;
    }
    int fDst[2];
    size_t fOff[2];
    #pragma unroll
    for (int q = 0; q < 2; q++) {
        int e = tid + q * 256, row = e >> 4, c4 = e & 15;
        fOff[q] = (size_t)row * HW + nBase + c4 * 4;
        fDst[q] = row * 256 + c4 * 16;
    }

    float acc[4][4][4];
    #pragma unroll
    for (int i = 0; i < 4; i++)
        #pragma unroll
        for (int j = 0; j < 4; j++)
            #pragma unroll
            for (int q = 0; q < 4; q++) acc[i][j][q] = 0.f;

    #define ISSUE1(ST, KO)                                                       \
        do {                                                                     \
            _Pragma("unroll")                                                    \
            for (int q = 0; q < 4; q++) {                                        \
                cpa16((ST) + AHI_OFF + aDst[q], Ahi_g + aOff[q] + (KO), true);   \
                cpa16((ST) + ALO_OFF + aDst[q], Alo_g + aOff[q] + (KO), true);   \
            }                                                                    \
            _Pragma("unroll")                                                    \
            for (int q = 0; q < 2; q++)                                          \
                cpa16((ST) + BF32_OFF + fDst[q],                                 \
                      fB + fOff[q] + (size_t)(KO) * HW, true);                   \
        } while (0)

    ISSUE1(sb, 0);
    cpa_commit();
    ISSUE1(sb + ST_STRIDE, 32);
    cpa_commit();

    const int lane15 = lane & 15;
    const int laneHi = lane >> 4;
    const int kB     = (lane >> 3) & 1;
    const int lane7  = lane & 7;
    const uint32_t aFragBase = (wm * 64 + lane15) * APITCH + laneHi * 16;
    const uint32_t bFragRow  = kB * 8 + lane7;
    const uint32_t bFragCol  = (wn * 32 + laneHi * 8) * 2;

    #pragma unroll 1
    for (int c = 0; c < 8; c++) {
        cpa_wait1();
        __syncthreads();
        const uint32_t st = sb + (c & 1) * ST_STRIDE;

        #pragma unroll
        for (int q = 0; q < 2; q++) {
            int e = tid + q * 256, row = e >> 4, c4 = e & 15;
            float4 v = *(const float4*)(smem + (c & 1) * ST_STRIDE + BF32_OFF
                                        + row * 256 + c4 * 16);
            __nv_bfloat16 h0, h1, h2, h3, l0, l1, l2, l3;
            split1(v.x, h0, l0); split1(v.y, h1, l1);
            split1(v.z, h2, l2); split1(v.w, h3, l3);
            *(uint2*)(smem + BHI_OFF + row * BPITCH + c4 * 8) =
                make_uint2(pk2(h0, h1), pk2(h2, h3));
            *(uint2*)(smem + BLO_OFF + row * BPITCH + c4 * 8) =
                make_uint2(pk2(l0, l1), pk2(l2, l3));
        }
        __syncthreads();

        #pragma unroll
        for (int ks = 0; ks < 2; ks++) {
            uint32_t ah[4][4], bh[4][2];
            #pragma unroll
            for (int i = 0; i < 4; i++)
                ldmx4(ah[i], st + AHI_OFF + aFragBase + i * 16 * APITCH + ks * 32);
            {
                uint32_t r[4];
                ldmx4t(r, sb + BHI_OFF + (ks * 16 + bFragRow) * BPITCH + bFragCol);
                bh[0][0] = r[0]; bh[0][1] = r[1]; bh[1][0] = r[2]; bh[1][1] = r[3];
                ldmx4t(r, sb + BHI_OFF + (ks * 16 + bFragRow) * BPITCH + bFragCol + 32);
                bh[2][0] = r[0]; bh[2][1] = r[1]; bh[3][0] = r[2]; bh[3][1] = r[3];
            }
            #pragma unroll
            for (int i = 0; i < 4; i++)
                #pragma unroll
                for (int j = 0; j < 4; j++)
                    mma16816(acc[i][j], ah[i], bh[j][0], bh[j][1]);
            {
                uint32_t bl[4][2], r[4];
                ldmx4t(r, sb + BLO_OFF + (ks * 16 + bFragRow) * BPITCH + bFragCol);
                bl[0][0] = r[0]; bl[0][1] = r[1]; bl[1][0] = r[2]; bl[1][1] = r[3];
                ldmx4t(r, sb + BLO_OFF + (ks * 16 + bFragRow) * BPITCH + bFragCol + 32);
                bl[2][0] = r[0]; bl[2][1] = r[1]; bl[3][0] = r[2]; bl[3][1] = r[3];
                #pragma unroll
                for (int i = 0; i < 4; i++)
                    #pragma unroll
                    for (int j = 0; j < 4; j++)
                        mma16816(acc[i][j], ah[i], bl[j][0], bl[j][1]);
            }
            {
                uint32_t al[4];
                #pragma unroll
                for (int i = 0; i < 4; i++) {
                    ldmx4(al, st + ALO_OFF + aFragBase + i * 16 * APITCH + ks * 32);
                    #pragma unroll
                    for (int j = 0; j < 4; j++)
                        mma16816(acc[i][j], al, bh[j][0], bh[j][1]);
                }
            }
        }
        __syncthreads();
        if (c + 2 < 8) ISSUE1(sb + (c & 1) * ST_STRIDE, (c + 2) * 32);
        cpa_commit();
    }
    #undef ISSUE1

    cpa_wait0();
    __syncthreads();

    const int w2r0 = tid >> 2, w2c0 = tid & 3;
    const int w2r1 = 64 + (tid >> 2), w2c1 = tid & 3;
    const bool w2a1 = tid < 64;
    const bool w2ok1 = w2a1 && (w2r1 < OUTCH);
    const int w2Off0 = w2r0 * KDIM + w2c0 * 8;
    const int w2Off1 = w2ok1 ? (w2r1 * KDIM + w2c1 * 8) : 0;
    const uint32_t w2Dst0 = w2r0 * 80 + w2c0 * 16;
    const uint32_t w2Dst1 = w2r1 * 80 + w2c1 * 16;

    #define ISSUE2(ST, KO)                                                       \
        do {                                                                     \
            cpa16((ST) + w2Dst0,        W2hi_g + w2Off0 + (KO), true);           \
            cpa16((ST) + 6400 + w2Dst0, W2lo_g + w2Off0 + (KO), true);           \
            if (w2a1) {                                                          \
                cpa16((ST) + w2Dst1,        W2hi_g + w2Off1 + (KO), w2ok1);      \
                cpa16((ST) + 6400 + w2Dst1, W2lo_g + w2Off1 + (KO), w2ok1);      \
            }                                                                    \
        } while (0)

    ISSUE2(sb + W2BASE, 0);
    cpa_commit();
    ISSUE2(sb + W2BASE + W2STG, 32);
    cpa_commit();

    const int g   = lane >> 2;
    const int tig = lane & 3;
    #pragma unroll
    for (int i = 0; i < 4; i++) {
        const int m0 = wm * 64 + i * 16 + g;
        const float bv0 = bias1[m0];
        const float bv1 = bias1[m0 + 8];
        #pragma unroll
        for (int j = 0; j < 4; j++) {
            const int p = wn * 32 + j * 8 + tig * 2;
            float f0 = acc[i][j][0] + bv0; f0 = f0 >= 0.f ? f0 : 0.01f * f0;
            float f1 = acc[i][j][1] + bv0; f1 = f1 >= 0.f ? f1 : 0.01f * f1;
            float f2 = acc[i][j][2] + bv1; f2 = f2 >= 0.f ? f2 : 0.01f * f2;
            float f3 = acc[i][j][3] + bv1; f3 = f3 >= 0.f ? f3 : 0.01f * f3;
            __nv_bfloat16 h0, h1, h2, h3, l0, l1, l2, l3;
            split1(f0, h0, l0); split1(f1, h1, l1);
            split1(f2, h2, l2); split1(f3, h3, l3);
            *(uint32_t*)(smem + HIDHI + m0 * BPITCH + p * 2)       = pk2(h0, h1);
            *(uint32_t*)(smem + HIDLO + m0 * BPITCH + p * 2)       = pk2(l0, l1);
            *(uint32_t*)(smem + HIDHI + (m0 + 8) * BPITCH + p * 2) = pk2(h2, h3);
            *(uint32_t*)(smem + HIDLO + (m0 + 8) * BPITCH + p * 2) = pk2(l2, l3);
        }
    }
    __syncthreads();

    const int mw = wid >> 1;
    const int nw = wid & 1;
    const int ibase = (mw == 0) ? 0 : (mw + 1);
    const int icnt  = (mw == 0) ? 2 : 1;

    float acc2[2][4][4];
    #pragma unroll
    for (int ii = 0; ii < 2; ii++)
        #pragma unroll
        for (int j = 0; j < 4; j++)
            #pragma unroll
            for (int q = 0; q < 4; q++) acc2[ii][j][q] = 0.f;

    const uint32_t a2Frag = lane15 * 80 + laneHi * 16;
    const uint32_t b2Col  = (nw * 32 + laneHi * 8) * 2;

    #pragma unroll 1
    for (int c = 0; c < 8; c++) {
        cpa_wait1();
        __syncthreads();
        const uint32_t st = sb + W2BASE + (c & 1) * W2STG;

        #pragma unroll
        for (int ks = 0; ks < 2; ks++) {
            const uint32_t hidRow = (c * 32 + ks * 16 + bFragRow) * BPITCH + b2Col;
            uint32_t bh[4][2], bl[4][2], r[4];
            ldmx4t(r, sb + HIDHI + hidRow);
            bh[0][0] = r[0]; bh[0][1] = r[1]; bh[1][0] = r[2]; bh[1][1] = r[3];
            ldmx4t(r, sb + HIDHI + hidRow + 32);
            bh[2][0] = r[0]; bh[2][1] = r[1]; bh[3][0] = r[2]; bh[3][1] = r[3];
            ldmx4t(r, sb + HIDLO + hidRow);
            bl[0][0] = r[0]; bl[0][1] = r[1]; bl[1][0] = r[2]; bl[1][1] = r[3];
            ldmx4t(r, sb + HIDLO + hidRow + 32);
            bl[2][0] = r[0]; bl[2][1] = r[1]; bl[3][0] = r[2]; bl[3][1] = r[3];

            #pragma unroll
            for (int ii = 0; ii < 2; ii++) {
                if (ii < icnt) {
                    const int i = ibase + ii;
                    uint32_t ah[4], al[4];
                    ldmx4(ah, st + a2Frag + i * 16 * 80 + ks * 32);
                    ldmx4(al, st + 6400 + a2Frag + i * 16 * 80 + ks * 32);
                    #pragma unroll
                    for (int j = 0; j < 4; j++) {
                        mma16816(acc2[ii][j], ah, bh[j][0], bh[j][1]);
                        mma16816(acc2[ii][j], ah, bl[j][0], bl[j][1]);
                        mma16816(acc2[ii][j], al, bh[j][0], bh[j][1]);
                    }
                }
            }
        }
        __syncthreads();
        if (c + 2 < 8) ISSUE2(sb + W2BASE + (c & 1) * W2STG, (c + 2) * 32);
        cpa_commit();
    }
    #undef ISSUE2

    #pragma unroll
    for (int ii = 0; ii < 2; ii++) {
        if (ii < icnt) {
            const int i = ibase + ii;
            const int m0 = i * 16 + g;
            const int m1 = m0 + 8;
            #pragma unroll
            for (int j = 0; j < 4; j++) {
                const int p = nBase + nw * 32 + j * 8 + tig * 2;
                if (m0 < OUTCH) {
                    const float bv = bias2[m0];
                    float2 v = make_float2(acc2[ii][j][0] + bv, acc2[ii][j][1] + bv);
                    *(float2*)&g_out2[((size_t)b * OUTCH + m0) * HW + p] = v;
                }
                if (m1 < OUTCH) {
                    const float bv = bias2[m1];
                    float2 v = make_float2(acc2[ii][j][2] + bv, acc2[ii][j][3] + bv);
                    *(float2*)&g_out2[((size_t)b * OUTCH + m1) * HW + p] = v;
                }
            }
        }
    }
}

// ---------------------------------------------------------------------------
// Head: issue-slot-optimized IoU. Boxes packed as float4 (1 LDS.128/box) +
// ga; fast division (__fdividef = RCP+MUL) replaces ~15-instr IEEE div.
// ---------------------------------------------------------------------------
__global__ __launch_bounds__(256)
void head_kernel(const float* __restrict__ anc,
                 const float* __restrict__ bboxes,
                 float* __restrict__ iou_out)
{
    __shared__ float4 box[NBOX];
    __shared__ float  ga[NBOX];
    const int b = blockIdx.z;
    const int a = blockIdx.y;
    const int tid  = threadIdx.x;
    const int wid  = tid >> 5;
    const int lane = tid & 31;

    if (tid < NBOX) {
        const float* bb = bboxes + ((size_t)b * NBOX + tid) * 5;
        float x1 = bb[0], y1 = bb[1], x2 = bb[2], y2 = bb[3];
        box[tid] = make_float4(x1, y1, x2, y2);
        ga[tid] = (x2 - x1) * (y2 - y1);
    }
    __syncthreads();

    const float wa = anc[a * 2 + 0], ha = anc[a * 2 + 1];
    const float* o = g_out2 + (size_t)b * OUTCH * HW;
    const int pBase = blockIdx.x * 128 + wid * 16;
    const int qmax = (HW - pBase) < 16 ? (HW - pBase) : 16;

    #pragma unroll 2
    for (int q = 0; q < qmax; q++) {
        int p = pBase + q;
        float tx = o[(5 * a + 1) * HW + p];
        float ty = o[(5 * a + 2) * HW + p];
        float tw = o[(5 * a + 3) * HW + p];
        float th = o[(5 * a + 4) * HW + p];
        int h = p / WW, w = p % WW;
        float cx = (w + 0.5f) + tx;
        float cy = (h + 0.5f) + ty;
        float nw = wa * __expf(tw);
        float nh = ha * __expf(th);
        float px1 = cx - nw * 0.5f, px2 = cx + nw * 0.5f;
        float py1 = cy - nh * 0.5f, py2 = cy + nh * 0.5f;
        float parea = (px2 - px1) * (py2 - py1);

        float* orow = iou_out + (((size_t)b * A_NUM + a) * HW + p) * NBOX;
        #pragma unroll
        for (int gg = 0; gg < 2; gg++) {
            int gi = lane + gg * 32;
            float4 bx = box[gi];
            float ix1 = fmaxf(px1, bx.x);
            float iy1 = fmaxf(py1, bx.y);
            float ix2 = fminf(px2, bx.z);
            float iy2 = fminf(py2, bx.w);
            float inter = fmaxf(ix2 - ix1, 0.f) * fmaxf(iy2 - iy1, 0.f);
            orow[gi] = __fdividef(inter, ga[gi] + parea - inter);
        }
    }
}

// ---------------------------------------------------------------------------
__global__ __launch_bounds__(64)
void loss_part(const int* __restrict__ pos_idx,
               const int* __restrict__ neg_idx,
               const float* __restrict__ gt_off)
{
    __shared__ float red[64];
    const int tid = threadIdx.x;
    const int m   = blockIdx.x * 64 + tid;
    float s = 0.f;
    {
        int idx = pos_idx[m];
        int b   = idx / (A_NUM * HW);
        int rem = idx % (A_NUM * HW);
        int a   = rem / HW;
        int p   = rem % HW;
        const float* o = g_out2 + ((size_t)b * OUTCH + 5 * a) * HW + p;
        float c  = o[0];
        float sc = 1.f / (1.f + expf(-c));
        float d  = sc - 1.f;
        s += 0.5f * d * d;
        #pragma unroll
        for (int k = 0; k < 4; k++) {
            float dd = o[(size_t)(1 + k) * HW] - gt_off[m * 4 + k];
            s += dd * dd;
        }
        int nidx = neg_idx[m];
        int nb   = nidx / (A_NUM * HW);
        int nrem = nidx % (A_NUM * HW);
        int na   = nrem / HW;
        int np   = nrem % HW;
        float nc = g_out2[((size_t)nb * OUTCH + 5 * na) * HW + np];
        float nsc = 1.f / (1.f + expf(-nc));
        s += 0.5f * nsc * nsc;
    }
    red[tid] = s;
    __syncthreads();
    for (int st = 32; st > 0; st >>= 1) {
        if (tid < st) red[tid] += red[tid + st];
        __syncthreads();
    }
    if (tid == 0) g_loss_part[blockIdx.x] = red[0];
}

__global__ void loss_final(float* __restrict__ out0)
{
    float s = 0.f;
    #pragma unroll
    for (int i = 0; i < 32; i++) s += g_loss_part[i];
    out0[0] = s / (float)MPOS;
}

// ---------------------------------------------------------------------------
__global__ __launch_bounds__(256)
void class_kernel(const int* __restrict__ pos_idx,
                  float* __restrict__ out_cls)
{
    int t = blockIdx.x * blockDim.x + threadIdx.x;
    if (t >= MPOS * C_NUM) return;
    int m = t / C_NUM;
    int c = t % C_NUM;
    int idx = pos_idx[m];
    int b = idx / (A_NUM * HW);
    int p = idx % HW;
    out_cls[t] = g_out2[((size_t)b * OUTCH + 5 * A_NUM + c) * HW + p];
}

// ---------------------------------------------------------------------------
extern "C" void kernel_launch(void* const* d_in, const int* in_sizes, int n_in,
                              void* d_out, int out_size)
{
    const float* features = (const float*)d_in[0];
    const float* w1       = (const float*)d_in[1];
    const float* b1       = (const float*)d_in[2];
    const float* w2       = (const float*)d_in[3];
    const float* b2       = (const float*)d_in[4];
    const float* anc      = (const float*)d_in[5];
    const float* bboxes   = (const float*)d_in[7];
    const float* gt_off   = (const float*)d_in[8];
    const int*   pos_idx  = (const int*)d_in[9];
    const int*   neg_idx  = (const int*)d_in[10];

    float* out      = (float*)d_out;
    float* loss_out = out;
    float* iou_out  = out + 1;
    float* cls_out  = out + 1 + (size_t)BATCH * A_NUM * HW * NBOX;

    cudaFuncSetAttribute(gemm_fused,
                         cudaFuncAttributeMaxDynamicSharedMemorySize, GEMM_SMEM);

    __nv_bfloat16 *w1h, *w1l, *w2h, *w2l;
    cudaGetSymbolAddress((void**)&w1h, g_w1_hi);
    cudaGetSymbolAddress((void**)&w1l, g_w1_lo);
    cudaGetSymbolAddress((void**)&w2h, g_w2_hi);
    cudaGetSymbolAddress((void**)&w2l, g_w2_lo);

    convert_split<<<(KDIM * KDIM / 4 + 255) / 256, 256>>>(w1, w1h, w1l, KDIM * KDIM / 4);
    convert_split<<<(OUTCH * KDIM / 4 + 255) / 256, 256>>>(w2, w2h, w2l, OUTCH * KDIM / 4);

    gemm_fused<<<dim3(49, 1, BATCH), 256, GEMM_SMEM>>>(w1h, w1l, features, b1,
                                                       w2h, w2l, b2);

    head_kernel<<<dim3(25, A_NUM, BATCH), 256>>>(anc, bboxes, iou_out);
    loss_part<<<32, 64>>>(pos_idx, neg_idx, gt_off);
    loss_final<<<1, 1>>>(loss_out);
    class_kernel<<<(MPOS * C_NUM + 255) / 256, 256>>>(pos_idx, cls_out);
}